// round 13
// baseline (speedup 1.0000x reference)
#include <cuda_runtime.h>
#include <cuda_fp16.h>
#include <stdint.h>
#include <math.h>

// ---------------------------------------------------------------------------
// DisentangledHierarchicalEncoder — mma.sync fp16 2-term split + compaction
//
//   A = Ah + Al (fp16 hi/lo), W ~= Wh (fp16). acc += Ah*Wh + Al*Wh = A*Wh.
//   Error = A*(W-Wh) ~ 2^-11 relative -> predicted final rel_err ~1e-4.
//   2 CTAs/SM (launch_bounds(256,2)), 2-stage cp.async, term-major MMAs.
//   Compaction: MLPs run only on catalog rows referenced by seq (~64%).
// ---------------------------------------------------------------------------

#define NUM_ITEM   50000
#define N_TOKENS   (1024 * 50)
#define NBLK_SCAN  196                   // 196*256 = 50176 >= NUM_ITEM+1

// ------------------------- device scratch (static) -------------------------
__device__ __half g_ahc[50000 * 1024];
__device__ __half g_alc[50000 * 1024];
__device__ __half g_aht[50000 * 768];
__device__ __half g_alt[50000 * 768];
__device__ __half g_h1h[50000 * 1024];
__device__ __half g_h1l[50000 * 1024];
__device__ __half g_h2h[50000 * 256];
__device__ __half g_h2l[50000 * 256];
__device__ __half g_w1c[1024 * 1024];
__device__ __half g_w1t[768 * 768];
__device__ __half g_w2c[256 * 1024];
__device__ __half g_w2t[256 * 768];
__device__ __half g_w3c[64 * 256];
__device__ __half g_w3t[64 * 256];
__device__ float g_cemb[50000 * 64];
__device__ float g_temb[50000 * 64];
__device__ float g_cfemb[50000 * 64];

// compaction state
__device__ int g_flag[NBLK_SCAN * 256];
__device__ int g_remap[NBLK_SCAN * 256];
__device__ int g_bsum[256];
__device__ int g_boff[256];
__device__ int g_count[1];

// ------------------------- small PTX helpers --------------------------------
__device__ __forceinline__ void cp16(uint32_t dst, const void* src, int sz) {
    asm volatile("cp.async.cg.shared.global [%0], [%1], 16, %2;"
                 :: "r"(dst), "l"(src), "r"(sz));
}
__device__ __forceinline__ void ldm4(uint32_t& r0, uint32_t& r1,
                                     uint32_t& r2, uint32_t& r3, uint32_t a) {
    asm volatile("ldmatrix.sync.aligned.m8n8.x4.shared.b16 {%0,%1,%2,%3}, [%4];"
                 : "=r"(r0), "=r"(r1), "=r"(r2), "=r"(r3) : "r"(a));
}
__device__ __forceinline__ void mma_f16(float* c, const uint32_t* a,
                                        const uint32_t* b) {
    asm volatile(
        "mma.sync.aligned.m16n8k16.row.col.f32.f16.f16.f32 "
        "{%0,%1,%2,%3}, {%4,%5,%6,%7}, {%8,%9}, {%0,%1,%2,%3};"
        : "+f"(c[0]), "+f"(c[1]), "+f"(c[2]), "+f"(c[3])
        : "r"(a[0]), "r"(a[1]), "r"(a[2]), "r"(a[3]), "r"(b[0]), "r"(b[1]));
}

// ------------------------- compaction kernels -------------------------------
__global__ void flag_clear_kernel() {
    g_flag[blockIdx.x * 256 + threadIdx.x] = 0;
}
__global__ void mark_kernel(const int* __restrict__ seq) {
    int i = blockIdx.x * 256 + threadIdx.x;
    if (i < N_TOKENS) {
        int v = seq[i];
        if (v >= NUM_ITEM) v = 0;
        g_flag[v] = 1;                       // benign races
    }
}
__global__ void scan_p1_kernel() {           // per-block sums
    __shared__ int s[256];
    int t = threadIdx.x, b = blockIdx.x;
    int i = b * 256 + t;
    int f = (i < NUM_ITEM) ? g_flag[i] : 0;
    s[t] = f; __syncthreads();
    for (int o = 128; o > 0; o >>= 1) {
        if (t < o) s[t] += s[t + o];
        __syncthreads();
    }
    if (t == 0) g_bsum[b] = s[0];
}
__global__ void scan_p2_kernel() {           // scan of block sums (1 block)
    __shared__ int s[256];
    int t = threadIdx.x;
    int v = (t < NBLK_SCAN) ? g_bsum[t] : 0;
    s[t] = v; __syncthreads();
    for (int o = 1; o < 256; o <<= 1) {
        int x = (t >= o) ? s[t - o] : 0;
        __syncthreads();
        s[t] += x;
        __syncthreads();
    }
    if (t < NBLK_SCAN) g_boff[t] = s[t] - v;   // exclusive
    if (t == 255) g_count[0] = s[255];
}
__global__ void scan_p3_kernel() {           // per-element remap
    __shared__ int s[256];
    int t = threadIdx.x, b = blockIdx.x;
    int i = b * 256 + t;
    int f = (i < NUM_ITEM) ? g_flag[i] : 0;
    s[t] = f; __syncthreads();
    for (int o = 1; o < 256; o <<= 1) {
        int x = (t >= o) ? s[t - o] : 0;
        __syncthreads();
        s[t] += x;
        __syncthreads();
    }
    if (f) g_remap[i] = g_boff[b] + s[t] - f;
}

// ------------------------- fused rownorm + fp16 hi/lo split (compacted) -----
__global__ void __launch_bounds__(128)
normsplit_kernel(const float* __restrict__ X, int K,
                 __half* __restrict__ hi, __half* __restrict__ lo)
{
    const int row = blockIdx.x;
    if (!g_flag[row]) return;
    const int orow = g_remap[row];
    const float4* x4 = reinterpret_cast<const float4*>(X + (size_t)row * K);
    const int K4 = K >> 2;
    float4 v[2];
    int cnt = 0;
    float s = 0.f;
    for (int i = threadIdx.x; i < K4; i += 128) {
        float4 t = x4[i];
        v[cnt++] = t;
        s += t.x * t.x + t.y * t.y + t.z * t.z + t.w * t.w;
    }
#pragma unroll
    for (int o = 16; o > 0; o >>= 1) s += __shfl_xor_sync(0xffffffffu, s, o);
    __shared__ float red[4];
    __shared__ float s_inv;
    int w = threadIdx.x >> 5;
    if ((threadIdx.x & 31) == 0) red[w] = s;
    __syncthreads();
    if (threadIdx.x == 0) {
        float t = red[0] + red[1] + red[2] + red[3];
        s_inv = 1.0f / fmaxf(sqrtf(t), 1e-12f);
    }
    __syncthreads();
    const float inv = s_inv;
    __half2* hrow = reinterpret_cast<__half2*>(hi + (size_t)orow * K);
    __half2* lrow = reinterpret_cast<__half2*>(lo + (size_t)orow * K);
    cnt = 0;
    for (int i = threadIdx.x; i < K4; i += 128) {
        float4 t = v[cnt++];
        t.x *= inv; t.y *= inv; t.z *= inv; t.w *= inv;
        __half hx = __float2half_rn(t.x), hy = __float2half_rn(t.y);
        __half hz = __float2half_rn(t.z), hw = __float2half_rn(t.w);
        __half2 h0; h0.x = hx; h0.y = hy;
        __half2 h1; h1.x = hz; h1.y = hw;
        __half2 l0, l1;
        l0.x = __float2half_rn(t.x - __half2float(hx));
        l0.y = __float2half_rn(t.y - __half2float(hy));
        l1.x = __float2half_rn(t.z - __half2float(hz));
        l1.y = __float2half_rn(t.w - __half2float(hw));
        hrow[2 * i] = h0; hrow[2 * i + 1] = h1;
        lrow[2 * i] = l0; lrow[2 * i + 1] = l1;
    }
}

// ------------------------- fp32 -> fp16 convert (weights, hi only) ----------
__global__ void convert_kernel(const float* __restrict__ X, long n4,
                               __half* __restrict__ out)
{
    long i = blockIdx.x * (long)blockDim.x + threadIdx.x;
    if (i >= n4) return;
    float4 v = reinterpret_cast<const float4*>(X)[i];
    __half2 h0, h1;
    h0.x = __float2half_rn(v.x); h0.y = __float2half_rn(v.y);
    h1.x = __float2half_rn(v.z); h1.y = __float2half_rn(v.w);
    reinterpret_cast<__half2*>(out)[2 * i]     = h0;
    reinterpret_cast<__half2*>(out)[2 * i + 1] = h1;
}

// ------------------------- tensor-core GEMM (mma.sync fp16, 2-term) ---------
// M is runtime: g_count[0] (compacted row count). Grid covers worst case.
template <int BN, int WARPS_M, int WARPS_N, bool RELU, bool OUT_SPLIT>
__global__ void __launch_bounds__(256, 2)
mma_gemm(int N, int K,
         const __half* __restrict__ Ah, const __half* __restrict__ Al,
         const __half* __restrict__ Wh,
         const float* __restrict__ bias,
         float* __restrict__ Cf,
         __half* __restrict__ Ch, __half* __restrict__ Cl)
{
    constexpr int BM = 128, BK = 32;
    constexpr int WM = BM / WARPS_M, WN = BN / WARPS_N;
    constexpr int MT = WM / 16, NT = WN / 8;
    constexpr int A_T = BM * 80;          // 80B padded rows (conflict-free)
    constexpr int W_T = BN * 80;
    constexpr int STAGE = 2 * A_T + W_T;
    constexpr int CH_A = BM * 4;          // 16B chunks per A tile
    constexpr int CH_W = BN * 4;
    constexpr int TOTAL = 2 * CH_A + CH_W;

    const int M = g_count[0];
    const int bm = blockIdx.y * BM, bn = blockIdx.x * BN;
    if (bm >= M) return;                  // compacted tail: nothing to do

    extern __shared__ char smem[];
    const uint32_t sb = (uint32_t)__cvta_generic_to_shared(smem);
    const int tid = threadIdx.x, lane = tid & 31, wid = tid >> 5;
    const int wm0 = (wid / WARPS_N) * WM;
    const int wn0 = (wid % WARPS_N) * WN;

    float acc[MT][NT][4];
#pragma unroll
    for (int m = 0; m < MT; ++m)
#pragma unroll
        for (int n = 0; n < NT; ++n)
#pragma unroll
            for (int j = 0; j < 4; ++j) acc[m][n][j] = 0.f;

    auto load_stage = [&](int s, int k0) {
        uint32_t d0 = sb + s * STAGE;
#pragma unroll
        for (int c = tid; c < TOTAL; c += 256) {
            const __half* src; uint32_t dst; int sz = 16;
            if (c < CH_A) {
                int r = c >> 2, q = c & 3, g = bm + r;
                sz = g < M ? 16 : 0; if (g >= M) g = M - 1;
                src = Ah + (size_t)g * K + k0 + q * 8;
                dst = d0 + r * 80 + q * 16;
            } else if (c < 2 * CH_A) {
                int cc = c - CH_A, r = cc >> 2, q = cc & 3, g = bm + r;
                sz = g < M ? 16 : 0; if (g >= M) g = M - 1;
                src = Al + (size_t)g * K + k0 + q * 8;
                dst = d0 + A_T + r * 80 + q * 16;
            } else {
                int cc = c - 2 * CH_A, r = cc >> 2, q = cc & 3;
                src = Wh + (size_t)(bn + r) * K + k0 + q * 8;
                dst = d0 + 2 * A_T + r * 80 + q * 16;
            }
            cp16(dst, src, sz);
        }
        asm volatile("cp.async.commit_group;");
    };

    const int nk = K / BK;
    load_stage(0, 0);

    for (int i = 0; i < nk; ++i) {
        if (i + 1 < nk) {
            load_stage((i + 1) & 1, (i + 1) * BK);
            asm volatile("cp.async.wait_group 1;");
        } else {
            asm volatile("cp.async.wait_group 0;");
        }
        __syncthreads();

        uint32_t aAh = sb + (i & 1) * STAGE;
        uint32_t aAl = aAh + A_T;
        uint32_t aWh = aAh + 2 * A_T;

#pragma unroll
        for (int kh = 0; kh < 2; ++kh) {
            uint32_t bh[NT][2];
#pragma unroll
            for (int nn = 0; nn < NT; nn += 2) {
                int r = wn0 + nn * 8 + (lane & 7) + ((lane >> 4) << 3);
                uint32_t kb = ((lane >> 3) & 1) * 16 + kh * 32;
                ldm4(bh[nn][0], bh[nn][1], bh[nn + 1][0], bh[nn + 1][1],
                     aWh + r * 80 + kb);
            }
#pragma unroll
            for (int mm = 0; mm < MT; ++mm) {
                int r = wm0 + mm * 16 + (lane & 7) + (((lane >> 3) & 1) << 3);
                uint32_t kb = ((lane >> 4) << 4) + kh * 32;
                uint32_t ah[4], al[4];
                ldm4(ah[0], ah[1], ah[2], ah[3], aAh + r * 80 + kb);
                ldm4(al[0], al[1], al[2], al[3], aAl + r * 80 + kb);
                // term-major: consecutive MMAs hit different accumulators
#pragma unroll
                for (int nn = 0; nn < NT; ++nn) mma_f16(acc[mm][nn], ah, bh[nn]);
#pragma unroll
                for (int nn = 0; nn < NT; ++nn) mma_f16(acc[mm][nn], al, bh[nn]);
            }
        }
        __syncthreads();
    }

    // epilogue
#pragma unroll
    for (int mm = 0; mm < MT; ++mm) {
#pragma unroll
        for (int nn = 0; nn < NT; ++nn) {
            int col = bn + wn0 + nn * 8 + (lane & 3) * 2;
            float b0 = __ldg(bias + col), b1 = __ldg(bias + col + 1);
#pragma unroll
            for (int h = 0; h < 2; ++h) {
                int row = bm + wm0 + mm * 16 + (lane >> 2) + h * 8;
                if (row < M) {
                    float r0 = acc[mm][nn][2 * h + 0] + b0;
                    float r1 = acc[mm][nn][2 * h + 1] + b1;
                    if (RELU) { r0 = fmaxf(r0, 0.f); r1 = fmaxf(r1, 0.f); }
                    if (OUT_SPLIT) {
                        __half h0 = __float2half_rn(r0);
                        __half h1 = __float2half_rn(r1);
                        __half l0 = __float2half_rn(r0 - __half2float(h0));
                        __half l1 = __float2half_rn(r1 - __half2float(h1));
                        __half2 vh; vh.x = h0; vh.y = h1;
                        __half2 vl; vl.x = l0; vl.y = l1;
                        *reinterpret_cast<__half2*>(&Ch[(size_t)row * N + col]) = vh;
                        *reinterpret_cast<__half2*>(&Cl[(size_t)row * N + col]) = vl;
                    } else {
                        *reinterpret_cast<float2*>(&Cf[(size_t)row * N + col]) =
                            make_float2(r0, r1);
                    }
                }
            }
        }
    }
}

// ------------------------- small SIMT GEMM (cf layer only) ------------------
template <int BM, int BN, int BK, int TM, int TN>
__global__ void __launch_bounds__((BM / TM) * (BN / TN))
sgemm_nt(int M, int N, int K,
         const float* __restrict__ A,
         const float* __restrict__ W,
         const float* __restrict__ bias,
         float* __restrict__ C)
{
    constexpr int NT = (BM / TM) * (BN / TN);
    constexpr int KQ = BK / 4;
    __shared__ float As[BK][BM];
    __shared__ float Ws[BK][BN];

    const int tid  = threadIdx.x;
    const int bm   = blockIdx.y * BM;
    const int bn   = blockIdx.x * BN;
    const int row0 = (tid / (BN / TN)) * TM;
    const int col0 = (tid % (BN / TN)) * TN;

    float acc[TM][TN];
#pragma unroll
    for (int i = 0; i < TM; ++i)
#pragma unroll
        for (int j = 0; j < TN; ++j) acc[i][j] = 0.f;

    for (int k0 = 0; k0 < K; k0 += BK) {
        for (int i = tid; i < BM * KQ; i += NT) {
            int r = i / KQ, q = i % KQ;
            int gr = bm + r;
            float4 v = make_float4(0.f, 0.f, 0.f, 0.f);
            if (gr < M)
                v = *reinterpret_cast<const float4*>(&A[(size_t)gr * K + k0 + 4 * q]);
            As[4 * q + 0][r] = v.x; As[4 * q + 1][r] = v.y;
            As[4 * q + 2][r] = v.z; As[4 * q + 3][r] = v.w;
        }
        for (int i = tid; i < BN * KQ; i += NT) {
            int r = i / KQ, q = i % KQ;
            int gr = bn + r;
            float4 v = make_float4(0.f, 0.f, 0.f, 0.f);
            if (gr < N)
                v = *reinterpret_cast<const float4*>(&W[(size_t)gr * K + k0 + 4 * q]);
            Ws[4 * q + 0][r] = v.x; Ws[4 * q + 1][r] = v.y;
            Ws[4 * q + 2][r] = v.z; Ws[4 * q + 3][r] = v.w;
        }
        __syncthreads();
#pragma unroll
        for (int k = 0; k < BK; ++k) {
            float ra[TM], rw[TN];
#pragma unroll
            for (int i = 0; i < TM; i += 4) {
                float4 v = *reinterpret_cast<const float4*>(&As[k][row0 + i]);
                ra[i] = v.x; ra[i + 1] = v.y; ra[i + 2] = v.z; ra[i + 3] = v.w;
            }
#pragma unroll
            for (int j = 0; j < TN; j += 4) {
                float4 v = *reinterpret_cast<const float4*>(&Ws[k][col0 + j]);
                rw[j] = v.x; rw[j + 1] = v.y; rw[j + 2] = v.z; rw[j + 3] = v.w;
            }
#pragma unroll
            for (int i = 0; i < TM; ++i)
#pragma unroll
                for (int j = 0; j < TN; ++j)
                    acc[i][j] = fmaf(ra[i], rw[j], acc[i][j]);
        }
        __syncthreads();
    }

#pragma unroll
    for (int i = 0; i < TM; ++i) {
        int gr = bm + row0 + i;
        if (gr < M) {
#pragma unroll
            for (int j = 0; j < TN; ++j) {
                int gc = bn + col0 + j;
                if (gc < N)
                    C[(size_t)gr * N + gc] = acc[i][j] + bias[gc];
            }
        }
    }
}

// ------------------------- attention: warp-per-4-tokens ---------------------
#define ATTN_TOK_ITERS 8                 // 4 warps * 4 tok * 8 = 128 tok/block
#define ATTN_SMEM_FLOATS (3 * 4096 + 4 * 4 * 4 * 64)
#define ATTN_SMEM_BYTES  (ATTN_SMEM_FLOATS * 4)

__global__ void __launch_bounds__(128)
attn_kernel(const int* __restrict__ seq,
            const float* __restrict__ cemb,     // compacted
            const float* __restrict__ temb,     // compacted
            const float* __restrict__ cfemb,    // full catalog
            const float* __restrict__ idemb,    // full catalog
            const float* __restrict__ wq,
            const float* __restrict__ wk,
            const float* __restrict__ wv,
            float* __restrict__ out)
{
    extern __shared__ float dyn[];
    float* w_s = dyn;                               // [3][64][64] transposed
    const int t = threadIdx.x;
    const int warp = t >> 5, lane = t & 31;
    float* xnw = dyn + 3 * 4096 + warp * 1024;      // [4 tok][4 modal][64]

    for (int i = t; i < 4096; i += 128) {
        int j = i >> 6, d = i & 63;
        w_s[0 * 4096 + d * 64 + j] = wq[i];
        w_s[1 * 4096 + d * 64 + j] = wk[i];
        w_s[2 * 4096 + d * 64 + j] = wv[i];
    }
    __syncthreads();

    const float* wqs = w_s;
    const float* wks = w_s + 4096;
    const float* wvs = w_s + 2 * 4096;

    for (int it = 0; it < ATTN_TOK_ITERS; ++it) {
        const int tok0 = (blockIdx.x * 4 + warp) * (4 * ATTN_TOK_ITERS) + it * 4;

        int idx[4], ridx[4];
#pragma unroll
        for (int tt = 0; tt < 4; ++tt) {
            int v = __ldg(&seq[tok0 + tt]);
            idx[tt] = (v >= NUM_ITEM) ? 0 : v;
            ridx[tt] = __ldg(&g_remap[idx[tt]]);
        }

        // ---- gather + l2norm + LayerNorm for 16 (token, modal) pairs
#pragma unroll
        for (int tm = 0; tm < 16; ++tm) {
            int tt = tm >> 2, m = tm & 3;
            const float* src =
                (m == 0) ? cemb + (size_t)ridx[tt] * 64 :
                (m == 1) ? temb + (size_t)ridx[tt] * 64 :
                (m == 2) ? cfemb + (size_t)idx[tt] * 64 :
                           idemb + (size_t)idx[tt] * 64;
            float2 e = *reinterpret_cast<const float2*>(src + 2 * lane);
            float ss = fmaf(e.x, e.x, e.y * e.y);
            float sm = e.x + e.y;
#pragma unroll
            for (int o = 16; o > 0; o >>= 1) {
                ss += __shfl_xor_sync(~0u, ss, o);
                sm += __shfl_xor_sync(~0u, sm, o);
            }
            float s  = 1.0f / fmaxf(sqrtf(ss), 1e-12f);
            float mu = s * sm * (1.0f / 64.0f);
            float var = s * s * ss * (1.0f / 64.0f) - mu * mu;
            float inv = 1.0f / sqrtf(var + 1e-5f);
            float d0 = (s * e.x - mu) * inv;
            float d1 = (s * e.y - mu) * inv;
            *reinterpret_cast<float2*>(&xnw[tm * 64 + 2 * lane]) =
                make_float2(d0, d1);
        }
        __syncwarp();

        // ---- q, k for all 16 (t,m): lane owns columns lane and lane+32
        float q0[16], q1[16], k0[16], k1[16];
#pragma unroll
        for (int tm = 0; tm < 16; ++tm) { q0[tm] = q1[tm] = k0[tm] = k1[tm] = 0.f; }
        for (int d = 0; d < 64; ++d) {
            float wqa = wqs[d * 64 + lane], wqb = wqs[d * 64 + lane + 32];
            float wka = wks[d * 64 + lane], wkb = wks[d * 64 + lane + 32];
#pragma unroll
            for (int tm = 0; tm < 16; ++tm) {
                float xv = xnw[tm * 64 + d];
                q0[tm] = fmaf(xv, wqa, q0[tm]);
                q1[tm] = fmaf(xv, wqb, q1[tm]);
                k0[tm] = fmaf(xv, wka, k0[tm]);
                k1[tm] = fmaf(xv, wkb, k1[tm]);
            }
        }

        // ---- scores + softmax -> pooled coefficients c[t][n]
        float cc[4][4];
#pragma unroll
        for (int tt = 0; tt < 4; ++tt) {
            float sc[4][4];
#pragma unroll
            for (int m = 0; m < 4; ++m)
#pragma unroll
                for (int n = 0; n < 4; ++n) {
                    float p = fmaf(q0[tt * 4 + m], k0[tt * 4 + n],
                                   q1[tt * 4 + m] * k1[tt * 4 + n]);
#pragma unroll
                    for (int o = 16; o > 0; o >>= 1) p += __shfl_xor_sync(~0u, p, o);
                    sc[m][n] = p * 0.125f;
                }
            float c0 = 0.f, c1 = 0.f, c2 = 0.f, c3 = 0.f;
#pragma unroll
            for (int m = 0; m < 4; ++m) {
                float mx = fmaxf(fmaxf(sc[m][0], sc[m][1]),
                                 fmaxf(sc[m][2], sc[m][3]));
                float e0 = expf(sc[m][0] - mx), e1 = expf(sc[m][1] - mx);
                float e2 = expf(sc[m][2] - mx), e3 = expf(sc[m][3] - mx);
                float rd = 1.0f / (e0 + e1 + e2 + e3);
                c0 = fmaf(e0, rd, c0); c1 = fmaf(e1, rd, c1);
                c2 = fmaf(e2, rd, c2); c3 = fmaf(e3, rd, c3);
            }
            cc[tt][0] = 0.25f * c0; cc[tt][1] = 0.25f * c1;
            cc[tt][2] = 0.25f * c2; cc[tt][3] = 0.25f * c3;
        }

        // ---- out[t] = (sum_n c_n * xn_n) @ wv^T  (cols lane, lane+32)
        float o0[4] = {0.f, 0.f, 0.f, 0.f}, o1[4] = {0.f, 0.f, 0.f, 0.f};
        for (int d = 0; d < 64; ++d) {
            float wva = wvs[d * 64 + lane], wvb = wvs[d * 64 + lane + 32];
#pragma unroll
            for (int tt = 0; tt < 4; ++tt) {
                float z = fmaf(cc[tt][0], xnw[(tt * 4 + 0) * 64 + d],
                          fmaf(cc[tt][1], xnw[(tt * 4 + 1) * 64 + d],
                          fmaf(cc[tt][2], xnw[(tt * 4 + 2) * 64 + d],
                               cc[tt][3] * xnw[(tt * 4 + 3) * 64 + d])));
                o0[tt] = fmaf(z, wva, o0[tt]);
                o1[tt] = fmaf(z, wvb, o1[tt]);
            }
        }
#pragma unroll
        for (int tt = 0; tt < 4; ++tt) {
            out[(size_t)(tok0 + tt) * 64 + lane]      = o0[tt];
            out[(size_t)(tok0 + tt) * 64 + lane + 32] = o1[tt];
        }
        __syncwarp();
    }
}

// ------------------------- launch ------------------------------------------
static inline int grid4(long n4) { return (int)((n4 + 255) / 256); }

extern "C" void kernel_launch(void* const* d_in, const int* in_sizes, int n_in,
                              void* d_out, int out_size)
{
    const int*   seq     = (const int*)d_in[0];
    const float* content = (const float*)d_in[1];
    const float* text    = (const float*)d_in[2];
    const float* cff     = (const float*)d_in[3];
    const float* idemb   = (const float*)d_in[4];
    const float* c_w1 = (const float*)d_in[5],  *c_b1 = (const float*)d_in[6];
    const float* c_w2 = (const float*)d_in[7],  *c_b2 = (const float*)d_in[8];
    const float* c_w3 = (const float*)d_in[9],  *c_b3 = (const float*)d_in[10];
    const float* t_w1 = (const float*)d_in[11], *t_b1 = (const float*)d_in[12];
    const float* t_w2 = (const float*)d_in[13], *t_b2 = (const float*)d_in[14];
    const float* t_w3 = (const float*)d_in[15], *t_b3 = (const float*)d_in[16];
    const float* cf_w = (const float*)d_in[17], *cf_b = (const float*)d_in[18];
    const float* wq   = (const float*)d_in[19];
    const float* wk   = (const float*)d_in[20];
    const float* wv   = (const float*)d_in[21];
    float* out = (float*)d_out;

    __half *ahc, *alc, *aht, *alt, *h1h, *h1l, *h2h, *h2l;
    __half *w1c, *w1t, *w2c, *w2t, *w3c, *w3t;
    float *cemb, *temb, *cfemb;
    cudaGetSymbolAddress((void**)&ahc, g_ahc);  cudaGetSymbolAddress((void**)&alc, g_alc);
    cudaGetSymbolAddress((void**)&aht, g_aht);  cudaGetSymbolAddress((void**)&alt, g_alt);
    cudaGetSymbolAddress((void**)&h1h, g_h1h);  cudaGetSymbolAddress((void**)&h1l, g_h1l);
    cudaGetSymbolAddress((void**)&h2h, g_h2h);  cudaGetSymbolAddress((void**)&h2l, g_h2l);
    cudaGetSymbolAddress((void**)&w1c, g_w1c);  cudaGetSymbolAddress((void**)&w1t, g_w1t);
    cudaGetSymbolAddress((void**)&w2c, g_w2c);  cudaGetSymbolAddress((void**)&w2t, g_w2t);
    cudaGetSymbolAddress((void**)&w3c, g_w3c);  cudaGetSymbolAddress((void**)&w3t, g_w3t);
    cudaGetSymbolAddress((void**)&cemb,  g_cemb);
    cudaGetSymbolAddress((void**)&temb,  g_temb);
    cudaGetSymbolAddress((void**)&cfemb, g_cfemb);

    const int gy = (NUM_ITEM + 127) / 128;   // 391 (worst-case M)

    const int SMEM_BN128 = 2 * (2 * 128 * 80 + 128 * 80);   // 61440
    const int SMEM_BN64  = 2 * (2 * 128 * 80 + 64 * 80);    // 51200
    cudaFuncSetAttribute((const void*)mma_gemm<128, 4, 2, true, true>,
                         cudaFuncAttributeMaxDynamicSharedMemorySize, SMEM_BN128);
    cudaFuncSetAttribute((const void*)mma_gemm<64, 4, 2, false, false>,
                         cudaFuncAttributeMaxDynamicSharedMemorySize, SMEM_BN64);
    cudaFuncSetAttribute(attn_kernel,
                         cudaFuncAttributeMaxDynamicSharedMemorySize, ATTN_SMEM_BYTES);

    // ---------------- compaction ----------------
    flag_clear_kernel<<<NBLK_SCAN, 256>>>();
    mark_kernel<<<(N_TOKENS + 255) / 256, 256>>>(seq);
    scan_p1_kernel<<<NBLK_SCAN, 256>>>();
    scan_p2_kernel<<<1, 256>>>();
    scan_p3_kernel<<<NBLK_SCAN, 256>>>();

    // ---------------- normsplits (compacted) + weight converts --------------
    normsplit_kernel<<<NUM_ITEM, 128>>>(content, 1024, ahc, alc);
    normsplit_kernel<<<NUM_ITEM, 128>>>(text, 768, aht, alt);
    convert_kernel<<<grid4(1024L * 1024 / 4), 256>>>(c_w1, 1024L * 1024 / 4, w1c);
    convert_kernel<<<grid4(256L * 1024 / 4), 256>>>(c_w2, 256L * 1024 / 4, w2c);
    convert_kernel<<<grid4(64L * 256 / 4), 256>>>(c_w3, 64L * 256 / 4, w3c);
    convert_kernel<<<grid4(768L * 768 / 4), 256>>>(t_w1, 768L * 768 / 4, w1t);
    convert_kernel<<<grid4(256L * 768 / 4), 256>>>(t_w2, 256L * 768 / 4, w2t);
    convert_kernel<<<grid4(64L * 256 / 4), 256>>>(t_w3, 64L * 256 / 4, w3t);

    // ---------------- content branch (M = g_count at runtime) ----------------
    mma_gemm<128, 4, 2, true, true><<<dim3(8, gy), 256, SMEM_BN128>>>(
        1024, 1024, ahc, alc, w1c, c_b1, nullptr, h1h, h1l);
    mma_gemm<128, 4, 2, true, true><<<dim3(2, gy), 256, SMEM_BN128>>>(
        256, 1024, h1h, h1l, w2c, c_b2, nullptr, h2h, h2l);
    mma_gemm<64, 4, 2, false, false><<<dim3(1, gy), 256, SMEM_BN64>>>(
        64, 256, h2h, h2l, w3c, c_b3, cemb, nullptr, nullptr);

    // ---------------- text branch ----------------
    mma_gemm<128, 4, 2, true, true><<<dim3(6, gy), 256, SMEM_BN128>>>(
        768, 768, aht, alt, w1t, t_b1, nullptr, h1h, h1l);
    mma_gemm<128, 4, 2, true, true><<<dim3(2, gy), 256, SMEM_BN128>>>(
        256, 768, h1h, h1l, w2t, t_b2, nullptr, h2h, h2l);
    mma_gemm<64, 4, 2, false, false><<<dim3(1, gy), 256, SMEM_BN64>>>(
        64, 256, h2h, h2l, w3t, t_b3, temb, nullptr, nullptr);

    // cf linear (tiny, full catalog)
    sgemm_nt<128, 64, 16, 8, 4><<<dim3(1, gy), 256>>>(
        NUM_ITEM, 64, 64, cff, cf_w, cf_b, cfemb);

    // fused gather + norm + attention (warp-per-4-tokens, remapped c/t)
    attn_kernel<<<N_TOKENS / 128, 128, ATTN_SMEM_BYTES>>>(
        seq, cemb, temb, cfemb, idemb, wq, wk, wv, out);
}

// round 14
// speedup vs baseline: 1.3423x; 1.3423x over previous
#include <cuda_runtime.h>
#include <cuda_fp16.h>
#include <stdint.h>
#include <math.h>

// ---------------------------------------------------------------------------
// DisentangledHierarchicalEncoder — R11 structure, fp16 2-term split GEMMs
//
//   A = Ah + Al (fp16 hi/lo), W ~= Wh (fp16). acc += Ah*Wh + Al*Wh.
//   Identical launch structure / tiling / occupancy config to the 1757us
//   R11 kernel; ONLY the GEMM arithmetic changed (isolated experiment).
//   Compaction: MLPs run only on catalog rows referenced by seq (~64%).
// ---------------------------------------------------------------------------

#define NUM_ITEM   50000
#define N_TOKENS   (1024 * 50)
#define NBLK_SCAN  196                   // 196*256 = 50176 >= NUM_ITEM+1

// ------------------------- device scratch (static) -------------------------
__device__ __half g_ahc[50000 * 1024];
__device__ __half g_alc[50000 * 1024];
__device__ __half g_aht[50000 * 768];
__device__ __half g_alt[50000 * 768];
__device__ __half g_h1h[50000 * 1024];
__device__ __half g_h1l[50000 * 1024];
__device__ __half g_h2h[50000 * 256];
__device__ __half g_h2l[50000 * 256];
__device__ __half g_w1c[1024 * 1024];
__device__ __half g_w1t[768 * 768];
__device__ __half g_w2c[256 * 1024];
__device__ __half g_w2t[256 * 768];
__device__ __half g_w3c[64 * 256];
__device__ __half g_w3t[64 * 256];
__device__ float g_cemb[50000 * 64];
__device__ float g_temb[50000 * 64];
__device__ float g_cfemb[50000 * 64];

// compaction state
__device__ int g_flag[NBLK_SCAN * 256];
__device__ int g_remap[NBLK_SCAN * 256];
__device__ int g_bsum[256];
__device__ int g_boff[256];
__device__ int g_count[1];

// ------------------------- small PTX helpers --------------------------------
__device__ __forceinline__ void cp16(uint32_t dst, const void* src, int sz) {
    asm volatile("cp.async.cg.shared.global [%0], [%1], 16, %2;"
                 :: "r"(dst), "l"(src), "r"(sz));
}
__device__ __forceinline__ void ldm4(uint32_t& r0, uint32_t& r1,
                                     uint32_t& r2, uint32_t& r3, uint32_t a) {
    asm volatile("ldmatrix.sync.aligned.m8n8.x4.shared.b16 {%0,%1,%2,%3}, [%4];"
                 : "=r"(r0), "=r"(r1), "=r"(r2), "=r"(r3) : "r"(a));
}
__device__ __forceinline__ void mma_f16(float* c, const uint32_t* a,
                                        const uint32_t* b) {
    asm volatile(
        "mma.sync.aligned.m16n8k16.row.col.f32.f16.f16.f32 "
        "{%0,%1,%2,%3}, {%4,%5,%6,%7}, {%8,%9}, {%0,%1,%2,%3};"
        : "+f"(c[0]), "+f"(c[1]), "+f"(c[2]), "+f"(c[3])
        : "r"(a[0]), "r"(a[1]), "r"(a[2]), "r"(a[3]), "r"(b[0]), "r"(b[1]));
}

// ------------------------- compaction kernels -------------------------------
__global__ void flag_clear_kernel() {
    g_flag[blockIdx.x * 256 + threadIdx.x] = 0;
}
__global__ void mark_kernel(const int* __restrict__ seq) {
    int i = blockIdx.x * 256 + threadIdx.x;
    if (i < N_TOKENS) {
        int v = seq[i];
        if (v >= NUM_ITEM) v = 0;
        g_flag[v] = 1;                       // benign races
    }
}
__global__ void scan_p1_kernel() {           // per-block sums
    __shared__ int s[256];
    int t = threadIdx.x, b = blockIdx.x;
    int i = b * 256 + t;
    int f = (i < NUM_ITEM) ? g_flag[i] : 0;
    s[t] = f; __syncthreads();
    for (int o = 128; o > 0; o >>= 1) {
        if (t < o) s[t] += s[t + o];
        __syncthreads();
    }
    if (t == 0) g_bsum[b] = s[0];
}
__global__ void scan_p2_kernel() {           // scan of block sums (1 block)
    __shared__ int s[256];
    int t = threadIdx.x;
    int v = (t < NBLK_SCAN) ? g_bsum[t] : 0;
    s[t] = v; __syncthreads();
    for (int o = 1; o < 256; o <<= 1) {
        int x = (t >= o) ? s[t - o] : 0;
        __syncthreads();
        s[t] += x;
        __syncthreads();
    }
    if (t < NBLK_SCAN) g_boff[t] = s[t] - v;   // exclusive
    if (t == 255) g_count[0] = s[255];
}
__global__ void scan_p3_kernel() {           // per-element remap
    __shared__ int s[256];
    int t = threadIdx.x, b = blockIdx.x;
    int i = b * 256 + t;
    int f = (i < NUM_ITEM) ? g_flag[i] : 0;
    s[t] = f; __syncthreads();
    for (int o = 1; o < 256; o <<= 1) {
        int x = (t >= o) ? s[t - o] : 0;
        __syncthreads();
        s[t] += x;
        __syncthreads();
    }
    if (f) g_remap[i] = g_boff[b] + s[t] - f;
}

// ------------------------- fused rownorm + fp16 hi/lo split (compacted) -----
__global__ void __launch_bounds__(128)
normsplit_kernel(const float* __restrict__ X, int K,
                 __half* __restrict__ hi, __half* __restrict__ lo)
{
    const int row = blockIdx.x;
    if (!g_flag[row]) return;
    const int orow = g_remap[row];
    const float4* x4 = reinterpret_cast<const float4*>(X + (size_t)row * K);
    const int K4 = K >> 2;
    float4 v[2];
    int cnt = 0;
    float s = 0.f;
    for (int i = threadIdx.x; i < K4; i += 128) {
        float4 t = x4[i];
        v[cnt++] = t;
        s += t.x * t.x + t.y * t.y + t.z * t.z + t.w * t.w;
    }
#pragma unroll
    for (int o = 16; o > 0; o >>= 1) s += __shfl_xor_sync(0xffffffffu, s, o);
    __shared__ float red[4];
    __shared__ float s_inv;
    int w = threadIdx.x >> 5;
    if ((threadIdx.x & 31) == 0) red[w] = s;
    __syncthreads();
    if (threadIdx.x == 0) {
        float t = red[0] + red[1] + red[2] + red[3];
        s_inv = 1.0f / fmaxf(sqrtf(t), 1e-12f);
    }
    __syncthreads();
    const float inv = s_inv;
    __half2* hrow = reinterpret_cast<__half2*>(hi + (size_t)orow * K);
    __half2* lrow = reinterpret_cast<__half2*>(lo + (size_t)orow * K);
    cnt = 0;
    for (int i = threadIdx.x; i < K4; i += 128) {
        float4 t = v[cnt++];
        t.x *= inv; t.y *= inv; t.z *= inv; t.w *= inv;
        __half hx = __float2half_rn(t.x), hy = __float2half_rn(t.y);
        __half hz = __float2half_rn(t.z), hw = __float2half_rn(t.w);
        __half2 h0; h0.x = hx; h0.y = hy;
        __half2 h1; h1.x = hz; h1.y = hw;
        __half2 l0, l1;
        l0.x = __float2half_rn(t.x - __half2float(hx));
        l0.y = __float2half_rn(t.y - __half2float(hy));
        l1.x = __float2half_rn(t.z - __half2float(hz));
        l1.y = __float2half_rn(t.w - __half2float(hw));
        hrow[2 * i] = h0; hrow[2 * i + 1] = h1;
        lrow[2 * i] = l0; lrow[2 * i + 1] = l1;
    }
}

// ------------------------- fp32 -> fp16 convert (weights, hi only) ----------
__global__ void convert_kernel(const float* __restrict__ X, long n4,
                               __half* __restrict__ out)
{
    long i = blockIdx.x * (long)blockDim.x + threadIdx.x;
    if (i >= n4) return;
    float4 v = reinterpret_cast<const float4*>(X)[i];
    __half2 h0, h1;
    h0.x = __float2half_rn(v.x); h0.y = __float2half_rn(v.y);
    h1.x = __float2half_rn(v.z); h1.y = __float2half_rn(v.w);
    reinterpret_cast<__half2*>(out)[2 * i]     = h0;
    reinterpret_cast<__half2*>(out)[2 * i + 1] = h1;
}

// ------------------------- tensor-core GEMM (mma.sync fp16, 2-term) ---------
// M is runtime: g_count[0] (compacted row count). Grid covers worst case.
// Tiling/occupancy config identical to the R11 (1757us) bf16 kernel.
template <int BN, int WARPS_M, int WARPS_N, bool RELU, bool OUT_SPLIT>
__global__ void __launch_bounds__(256)
mma_gemm(int N, int K,
         const __half* __restrict__ Ah, const __half* __restrict__ Al,
         const __half* __restrict__ Wh,
         const float* __restrict__ bias,
         float* __restrict__ Cf,
         __half* __restrict__ Ch, __half* __restrict__ Cl)
{
    constexpr int BM = 128, BK = 32;
    constexpr int WM = BM / WARPS_M, WN = BN / WARPS_N;
    constexpr int MT = WM / 16, NT = WN / 8;
    constexpr int A_T = BM * 80;          // 80B padded rows (conflict-free)
    constexpr int W_T = BN * 80;
    constexpr int STAGE = 2 * A_T + W_T;
    constexpr int CH_A = BM * 4;          // 16B chunks per A tile
    constexpr int CH_W = BN * 4;
    constexpr int TOTAL = 2 * CH_A + CH_W;

    const int M = g_count[0];
    const int bm = blockIdx.y * BM, bn = blockIdx.x * BN;
    if (bm >= M) return;                  // compacted tail: nothing to do

    extern __shared__ char smem[];
    const uint32_t sb = (uint32_t)__cvta_generic_to_shared(smem);
    const int tid = threadIdx.x, lane = tid & 31, wid = tid >> 5;
    const int wm0 = (wid / WARPS_N) * WM;
    const int wn0 = (wid % WARPS_N) * WN;

    float acc[MT][NT][4];
#pragma unroll
    for (int m = 0; m < MT; ++m)
#pragma unroll
        for (int n = 0; n < NT; ++n)
#pragma unroll
            for (int j = 0; j < 4; ++j) acc[m][n][j] = 0.f;

    auto load_stage = [&](int s, int k0) {
        uint32_t d0 = sb + s * STAGE;
#pragma unroll
        for (int c = tid; c < TOTAL; c += 256) {
            const __half* src; uint32_t dst; int sz = 16;
            if (c < CH_A) {
                int r = c >> 2, q = c & 3, g = bm + r;
                sz = g < M ? 16 : 0; if (g >= M) g = M - 1;
                src = Ah + (size_t)g * K + k0 + q * 8;
                dst = d0 + r * 80 + q * 16;
            } else if (c < 2 * CH_A) {
                int cc = c - CH_A, r = cc >> 2, q = cc & 3, g = bm + r;
                sz = g < M ? 16 : 0; if (g >= M) g = M - 1;
                src = Al + (size_t)g * K + k0 + q * 8;
                dst = d0 + A_T + r * 80 + q * 16;
            } else {
                int cc = c - 2 * CH_A, r = cc >> 2, q = cc & 3;
                src = Wh + (size_t)(bn + r) * K + k0 + q * 8;
                dst = d0 + 2 * A_T + r * 80 + q * 16;
            }
            cp16(dst, src, sz);
        }
        asm volatile("cp.async.commit_group;");
    };

    const int nk = K / BK;
    load_stage(0, 0);

    for (int i = 0; i < nk; ++i) {
        if (i + 1 < nk) {
            load_stage((i + 1) & 1, (i + 1) * BK);
            asm volatile("cp.async.wait_group 1;");
        } else {
            asm volatile("cp.async.wait_group 0;");
        }
        __syncthreads();

        uint32_t aAh = sb + (i & 1) * STAGE;
        uint32_t aAl = aAh + A_T;
        uint32_t aWh = aAh + 2 * A_T;

#pragma unroll
        for (int kh = 0; kh < 2; ++kh) {
            uint32_t bh[NT][2];
#pragma unroll
            for (int nn = 0; nn < NT; nn += 2) {
                int r = wn0 + nn * 8 + (lane & 7) + ((lane >> 4) << 3);
                uint32_t kb = ((lane >> 3) & 1) * 16 + kh * 32;
                ldm4(bh[nn][0], bh[nn][1], bh[nn + 1][0], bh[nn + 1][1],
                     aWh + r * 80 + kb);
            }
#pragma unroll
            for (int mm = 0; mm < MT; ++mm) {
                int r = wm0 + mm * 16 + (lane & 7) + (((lane >> 3) & 1) << 3);
                uint32_t kb = ((lane >> 4) << 4) + kh * 32;
                uint32_t ah[4], al[4];
                ldm4(ah[0], ah[1], ah[2], ah[3], aAh + r * 80 + kb);
                ldm4(al[0], al[1], al[2], al[3], aAl + r * 80 + kb);
                // term-major: consecutive MMAs hit different accumulators
#pragma unroll
                for (int nn = 0; nn < NT; ++nn) mma_f16(acc[mm][nn], ah, bh[nn]);
#pragma unroll
                for (int nn = 0; nn < NT; ++nn) mma_f16(acc[mm][nn], al, bh[nn]);
            }
        }
        __syncthreads();
    }

    // epilogue
#pragma unroll
    for (int mm = 0; mm < MT; ++mm) {
#pragma unroll
        for (int nn = 0; nn < NT; ++nn) {
            int col = bn + wn0 + nn * 8 + (lane & 3) * 2;
            float b0 = __ldg(bias + col), b1 = __ldg(bias + col + 1);
#pragma unroll
            for (int h = 0; h < 2; ++h) {
                int row = bm + wm0 + mm * 16 + (lane >> 2) + h * 8;
                if (row < M) {
                    float r0 = acc[mm][nn][2 * h + 0] + b0;
                    float r1 = acc[mm][nn][2 * h + 1] + b1;
                    if (RELU) { r0 = fmaxf(r0, 0.f); r1 = fmaxf(r1, 0.f); }
                    if (OUT_SPLIT) {
                        __half h0 = __float2half_rn(r0);
                        __half h1 = __float2half_rn(r1);
                        __half l0 = __float2half_rn(r0 - __half2float(h0));
                        __half l1 = __float2half_rn(r1 - __half2float(h1));
                        __half2 vh; vh.x = h0; vh.y = h1;
                        __half2 vl; vl.x = l0; vl.y = l1;
                        *reinterpret_cast<__half2*>(&Ch[(size_t)row * N + col]) = vh;
                        *reinterpret_cast<__half2*>(&Cl[(size_t)row * N + col]) = vl;
                    } else {
                        *reinterpret_cast<float2*>(&Cf[(size_t)row * N + col]) =
                            make_float2(r0, r1);
                    }
                }
            }
        }
    }
}

// ------------------------- small SIMT GEMM (cf layer only) ------------------
template <int BM, int BN, int BK, int TM, int TN>
__global__ void __launch_bounds__((BM / TM) * (BN / TN))
sgemm_nt(int M, int N, int K,
         const float* __restrict__ A,
         const float* __restrict__ W,
         const float* __restrict__ bias,
         float* __restrict__ C)
{
    constexpr int NT = (BM / TM) * (BN / TN);
    constexpr int KQ = BK / 4;
    __shared__ float As[BK][BM];
    __shared__ float Ws[BK][BN];

    const int tid  = threadIdx.x;
    const int bm   = blockIdx.y * BM;
    const int bn   = blockIdx.x * BN;
    const int row0 = (tid / (BN / TN)) * TM;
    const int col0 = (tid % (BN / TN)) * TN;

    float acc[TM][TN];
#pragma unroll
    for (int i = 0; i < TM; ++i)
#pragma unroll
        for (int j = 0; j < TN; ++j) acc[i][j] = 0.f;

    for (int k0 = 0; k0 < K; k0 += BK) {
        for (int i = tid; i < BM * KQ; i += NT) {
            int r = i / KQ, q = i % KQ;
            int gr = bm + r;
            float4 v = make_float4(0.f, 0.f, 0.f, 0.f);
            if (gr < M)
                v = *reinterpret_cast<const float4*>(&A[(size_t)gr * K + k0 + 4 * q]);
            As[4 * q + 0][r] = v.x; As[4 * q + 1][r] = v.y;
            As[4 * q + 2][r] = v.z; As[4 * q + 3][r] = v.w;
        }
        for (int i = tid; i < BN * KQ; i += NT) {
            int r = i / KQ, q = i % KQ;
            int gr = bn + r;
            float4 v = make_float4(0.f, 0.f, 0.f, 0.f);
            if (gr < N)
                v = *reinterpret_cast<const float4*>(&W[(size_t)gr * K + k0 + 4 * q]);
            Ws[4 * q + 0][r] = v.x; Ws[4 * q + 1][r] = v.y;
            Ws[4 * q + 2][r] = v.z; Ws[4 * q + 3][r] = v.w;
        }
        __syncthreads();
#pragma unroll
        for (int k = 0; k < BK; ++k) {
            float ra[TM], rw[TN];
#pragma unroll
            for (int i = 0; i < TM; i += 4) {
                float4 v = *reinterpret_cast<const float4*>(&As[k][row0 + i]);
                ra[i] = v.x; ra[i + 1] = v.y; ra[i + 2] = v.z; ra[i + 3] = v.w;
            }
#pragma unroll
            for (int j = 0; j < TN; j += 4) {
                float4 v = *reinterpret_cast<const float4*>(&Ws[k][col0 + j]);
                rw[j] = v.x; rw[j + 1] = v.y; rw[j + 2] = v.z; rw[j + 3] = v.w;
            }
#pragma unroll
            for (int i = 0; i < TM; ++i)
#pragma unroll
                for (int j = 0; j < TN; ++j)
                    acc[i][j] = fmaf(ra[i], rw[j], acc[i][j]);
        }
        __syncthreads();
    }

#pragma unroll
    for (int i = 0; i < TM; ++i) {
        int gr = bm + row0 + i;
        if (gr < M) {
#pragma unroll
            for (int j = 0; j < TN; ++j) {
                int gc = bn + col0 + j;
                if (gc < N)
                    C[(size_t)gr * N + gc] = acc[i][j] + bias[gc];
            }
        }
    }
}

// ------------------------- attention: warp-per-4-tokens ---------------------
#define ATTN_TOK_ITERS 8                 // 4 warps * 4 tok * 8 = 128 tok/block
#define ATTN_SMEM_FLOATS (3 * 4096 + 4 * 4 * 4 * 64)
#define ATTN_SMEM_BYTES  (ATTN_SMEM_FLOATS * 4)

__global__ void __launch_bounds__(128)
attn_kernel(const int* __restrict__ seq,
            const float* __restrict__ cemb,     // compacted
            const float* __restrict__ temb,     // compacted
            const float* __restrict__ cfemb,    // full catalog
            const float* __restrict__ idemb,    // full catalog
            const float* __restrict__ wq,
            const float* __restrict__ wk,
            const float* __restrict__ wv,
            float* __restrict__ out)
{
    extern __shared__ float dyn[];
    float* w_s = dyn;                               // [3][64][64] transposed
    const int t = threadIdx.x;
    const int warp = t >> 5, lane = t & 31;
    float* xnw = dyn + 3 * 4096 + warp * 1024;      // [4 tok][4 modal][64]

    for (int i = t; i < 4096; i += 128) {
        int j = i >> 6, d = i & 63;
        w_s[0 * 4096 + d * 64 + j] = wq[i];
        w_s[1 * 4096 + d * 64 + j] = wk[i];
        w_s[2 * 4096 + d * 64 + j] = wv[i];
    }
    __syncthreads();

    const float* wqs = w_s;
    const float* wks = w_s + 4096;
    const float* wvs = w_s + 2 * 4096;

    for (int it = 0; it < ATTN_TOK_ITERS; ++it) {
        const int tok0 = (blockIdx.x * 4 + warp) * (4 * ATTN_TOK_ITERS) + it * 4;

        int idx[4], ridx[4];
#pragma unroll
        for (int tt = 0; tt < 4; ++tt) {
            int v = __ldg(&seq[tok0 + tt]);
            idx[tt] = (v >= NUM_ITEM) ? 0 : v;
            ridx[tt] = __ldg(&g_remap[idx[tt]]);
        }

        // ---- gather + l2norm + LayerNorm for 16 (token, modal) pairs
#pragma unroll
        for (int tm = 0; tm < 16; ++tm) {
            int tt = tm >> 2, m = tm & 3;
            const float* src =
                (m == 0) ? cemb + (size_t)ridx[tt] * 64 :
                (m == 1) ? temb + (size_t)ridx[tt] * 64 :
                (m == 2) ? cfemb + (size_t)idx[tt] * 64 :
                           idemb + (size_t)idx[tt] * 64;
            float2 e = *reinterpret_cast<const float2*>(src + 2 * lane);
            float ss = fmaf(e.x, e.x, e.y * e.y);
            float sm = e.x + e.y;
#pragma unroll
            for (int o = 16; o > 0; o >>= 1) {
                ss += __shfl_xor_sync(~0u, ss, o);
                sm += __shfl_xor_sync(~0u, sm, o);
            }
            float s  = 1.0f / fmaxf(sqrtf(ss), 1e-12f);
            float mu = s * sm * (1.0f / 64.0f);
            float var = s * s * ss * (1.0f / 64.0f) - mu * mu;
            float inv = 1.0f / sqrtf(var + 1e-5f);
            float d0 = (s * e.x - mu) * inv;
            float d1 = (s * e.y - mu) * inv;
            *reinterpret_cast<float2*>(&xnw[tm * 64 + 2 * lane]) =
                make_float2(d0, d1);
        }
        __syncwarp();

        // ---- q, k for all 16 (t,m): lane owns columns lane and lane+32
        float q0[16], q1[16], k0[16], k1[16];
#pragma unroll
        for (int tm = 0; tm < 16; ++tm) { q0[tm] = q1[tm] = k0[tm] = k1[tm] = 0.f; }
        for (int d = 0; d < 64; ++d) {
            float wqa = wqs[d * 64 + lane], wqb = wqs[d * 64 + lane + 32];
            float wka = wks[d * 64 + lane], wkb = wks[d * 64 + lane + 32];
#pragma unroll
            for (int tm = 0; tm < 16; ++tm) {
                float xv = xnw[tm * 64 + d];
                q0[tm] = fmaf(xv, wqa, q0[tm]);
                q1[tm] = fmaf(xv, wqb, q1[tm]);
                k0[tm] = fmaf(xv, wka, k0[tm]);
                k1[tm] = fmaf(xv, wkb, k1[tm]);
            }
        }

        // ---- scores + softmax -> pooled coefficients c[t][n]
        float cc[4][4];
#pragma unroll
        for (int tt = 0; tt < 4; ++tt) {
            float sc[4][4];
#pragma unroll
            for (int m = 0; m < 4; ++m)
#pragma unroll
                for (int n = 0; n < 4; ++n) {
                    float p = fmaf(q0[tt * 4 + m], k0[tt * 4 + n],
                                   q1[tt * 4 + m] * k1[tt * 4 + n]);
#pragma unroll
                    for (int o = 16; o > 0; o >>= 1) p += __shfl_xor_sync(~0u, p, o);
                    sc[m][n] = p * 0.125f;
                }
            float c0 = 0.f, c1 = 0.f, c2 = 0.f, c3 = 0.f;
#pragma unroll
            for (int m = 0; m < 4; ++m) {
                float mx = fmaxf(fmaxf(sc[m][0], sc[m][1]),
                                 fmaxf(sc[m][2], sc[m][3]));
                float e0 = expf(sc[m][0] - mx), e1 = expf(sc[m][1] - mx);
                float e2 = expf(sc[m][2] - mx), e3 = expf(sc[m][3] - mx);
                float rd = 1.0f / (e0 + e1 + e2 + e3);
                c0 = fmaf(e0, rd, c0); c1 = fmaf(e1, rd, c1);
                c2 = fmaf(e2, rd, c2); c3 = fmaf(e3, rd, c3);
            }
            cc[tt][0] = 0.25f * c0; cc[tt][1] = 0.25f * c1;
            cc[tt][2] = 0.25f * c2; cc[tt][3] = 0.25f * c3;
        }

        // ---- out[t] = (sum_n c_n * xn_n) @ wv^T  (cols lane, lane+32)
        float o0[4] = {0.f, 0.f, 0.f, 0.f}, o1[4] = {0.f, 0.f, 0.f, 0.f};
        for (int d = 0; d < 64; ++d) {
            float wva = wvs[d * 64 + lane], wvb = wvs[d * 64 + lane + 32];
#pragma unroll
            for (int tt = 0; tt < 4; ++tt) {
                float z = fmaf(cc[tt][0], xnw[(tt * 4 + 0) * 64 + d],
                          fmaf(cc[tt][1], xnw[(tt * 4 + 1) * 64 + d],
                          fmaf(cc[tt][2], xnw[(tt * 4 + 2) * 64 + d],
                               cc[tt][3] * xnw[(tt * 4 + 3) * 64 + d])));
                o0[tt] = fmaf(z, wva, o0[tt]);
                o1[tt] = fmaf(z, wvb, o1[tt]);
            }
        }
#pragma unroll
        for (int tt = 0; tt < 4; ++tt) {
            out[(size_t)(tok0 + tt) * 64 + lane]      = o0[tt];
            out[(size_t)(tok0 + tt) * 64 + lane + 32] = o1[tt];
        }
        __syncwarp();
    }
}

// ------------------------- launch ------------------------------------------
static inline int grid4(long n4) { return (int)((n4 + 255) / 256); }

extern "C" void kernel_launch(void* const* d_in, const int* in_sizes, int n_in,
                              void* d_out, int out_size)
{
    const int*   seq     = (const int*)d_in[0];
    const float* content = (const float*)d_in[1];
    const float* text    = (const float*)d_in[2];
    const float* cff     = (const float*)d_in[3];
    const float* idemb   = (const float*)d_in[4];
    const float* c_w1 = (const float*)d_in[5],  *c_b1 = (const float*)d_in[6];
    const float* c_w2 = (const float*)d_in[7],  *c_b2 = (const float*)d_in[8];
    const float* c_w3 = (const float*)d_in[9],  *c_b3 = (const float*)d_in[10];
    const float* t_w1 = (const float*)d_in[11], *t_b1 = (const float*)d_in[12];
    const float* t_w2 = (const float*)d_in[13], *t_b2 = (const float*)d_in[14];
    const float* t_w3 = (const float*)d_in[15], *t_b3 = (const float*)d_in[16];
    const float* cf_w = (const float*)d_in[17], *cf_b = (const float*)d_in[18];
    const float* wq   = (const float*)d_in[19];
    const float* wk   = (const float*)d_in[20];
    const float* wv   = (const float*)d_in[21];
    float* out = (float*)d_out;

    __half *ahc, *alc, *aht, *alt, *h1h, *h1l, *h2h, *h2l;
    __half *w1c, *w1t, *w2c, *w2t, *w3c, *w3t;
    float *cemb, *temb, *cfemb;
    cudaGetSymbolAddress((void**)&ahc, g_ahc);  cudaGetSymbolAddress((void**)&alc, g_alc);
    cudaGetSymbolAddress((void**)&aht, g_aht);  cudaGetSymbolAddress((void**)&alt, g_alt);
    cudaGetSymbolAddress((void**)&h1h, g_h1h);  cudaGetSymbolAddress((void**)&h1l, g_h1l);
    cudaGetSymbolAddress((void**)&h2h, g_h2h);  cudaGetSymbolAddress((void**)&h2l, g_h2l);
    cudaGetSymbolAddress((void**)&w1c, g_w1c);  cudaGetSymbolAddress((void**)&w1t, g_w1t);
    cudaGetSymbolAddress((void**)&w2c, g_w2c);  cudaGetSymbolAddress((void**)&w2t, g_w2t);
    cudaGetSymbolAddress((void**)&w3c, g_w3c);  cudaGetSymbolAddress((void**)&w3t, g_w3t);
    cudaGetSymbolAddress((void**)&cemb,  g_cemb);
    cudaGetSymbolAddress((void**)&temb,  g_temb);
    cudaGetSymbolAddress((void**)&cfemb, g_cfemb);

    const int gy = (NUM_ITEM + 127) / 128;   // 391 (worst-case M)

    const int SMEM_BN128 = 2 * (2 * 128 * 80 + 128 * 80);   // 61440
    const int SMEM_BN64  = 2 * (2 * 128 * 80 + 64 * 80);    // 51200
    cudaFuncSetAttribute((const void*)mma_gemm<128, 2, 4, true, true>,
                         cudaFuncAttributeMaxDynamicSharedMemorySize, SMEM_BN128);
    cudaFuncSetAttribute((const void*)mma_gemm<64, 4, 2, false, false>,
                         cudaFuncAttributeMaxDynamicSharedMemorySize, SMEM_BN64);
    cudaFuncSetAttribute(attn_kernel,
                         cudaFuncAttributeMaxDynamicSharedMemorySize, ATTN_SMEM_BYTES);

    // ---------------- compaction ----------------
    flag_clear_kernel<<<NBLK_SCAN, 256>>>();
    mark_kernel<<<(N_TOKENS + 255) / 256, 256>>>(seq);
    scan_p1_kernel<<<NBLK_SCAN, 256>>>();
    scan_p2_kernel<<<1, 256>>>();
    scan_p3_kernel<<<NBLK_SCAN, 256>>>();

    // ---------------- normsplits (compacted) + weight converts --------------
    normsplit_kernel<<<NUM_ITEM, 128>>>(content, 1024, ahc, alc);
    normsplit_kernel<<<NUM_ITEM, 128>>>(text, 768, aht, alt);
    convert_kernel<<<grid4(1024L * 1024 / 4), 256>>>(c_w1, 1024L * 1024 / 4, w1c);
    convert_kernel<<<grid4(256L * 1024 / 4), 256>>>(c_w2, 256L * 1024 / 4, w2c);
    convert_kernel<<<grid4(64L * 256 / 4), 256>>>(c_w3, 64L * 256 / 4, w3c);
    convert_kernel<<<grid4(768L * 768 / 4), 256>>>(t_w1, 768L * 768 / 4, w1t);
    convert_kernel<<<grid4(256L * 768 / 4), 256>>>(t_w2, 256L * 768 / 4, w2t);
    convert_kernel<<<grid4(64L * 256 / 4), 256>>>(t_w3, 64L * 256 / 4, w3t);

    // ---------------- content branch (M = g_count at runtime) ----------------
    mma_gemm<128, 2, 4, true, true><<<dim3(8, gy), 256, SMEM_BN128>>>(
        1024, 1024, ahc, alc, w1c, c_b1, nullptr, h1h, h1l);
    mma_gemm<128, 2, 4, true, true><<<dim3(2, gy), 256, SMEM_BN128>>>(
        256, 1024, h1h, h1l, w2c, c_b2, nullptr, h2h, h2l);
    mma_gemm<64, 4, 2, false, false><<<dim3(1, gy), 256, SMEM_BN64>>>(
        64, 256, h2h, h2l, w3c, c_b3, cemb, nullptr, nullptr);

    // ---------------- text branch ----------------
    mma_gemm<128, 2, 4, true, true><<<dim3(6, gy), 256, SMEM_BN128>>>(
        768, 768, aht, alt, w1t, t_b1, nullptr, h1h, h1l);
    mma_gemm<128, 2, 4, true, true><<<dim3(2, gy), 256, SMEM_BN128>>>(
        256, 768, h1h, h1l, w2t, t_b2, nullptr, h2h, h2l);
    mma_gemm<64, 4, 2, false, false><<<dim3(1, gy), 256, SMEM_BN64>>>(
        64, 256, h2h, h2l, w3t, t_b3, temb, nullptr, nullptr);

    // cf linear (tiny, full catalog)
    sgemm_nt<128, 64, 16, 8, 4><<<dim3(1, gy), 256>>>(
        NUM_ITEM, 64, 64, cff, cf_w, cf_b, cfemb);

    // fused gather + norm + attention (warp-per-4-tokens, remapped c/t)
    attn_kernel<<<N_TOKENS / 128, 128, ATTN_SMEM_BYTES>>>(
        seq, cemb, temb, cfemb, idemb, wq, wk, wv, out);
}

// round 15
// speedup vs baseline: 1.4059x; 1.0474x over previous
#include <cuda_runtime.h>
#include <cuda_fp16.h>
#include <stdint.h>
#include <math.h>

// ---------------------------------------------------------------------------
// DisentangledHierarchicalEncoder — fp16 2-term GEMMs + compaction + per-item
// attention dedup: out[tok] is a pure function of the item id, so attention
// runs once per unique item (~64% of tokens) and a scatter expands to tokens.
// ---------------------------------------------------------------------------

#define NUM_ITEM   50000
#define N_TOKENS   (1024 * 50)
#define NBLK_SCAN  196                   // 196*256 = 50176 >= NUM_ITEM+1

// ------------------------- device scratch (static) -------------------------
__device__ __half g_ahc[50000 * 1024];
__device__ __half g_alc[50000 * 1024];
__device__ __half g_aht[50000 * 768];
__device__ __half g_alt[50000 * 768];
__device__ __half g_h1h[50000 * 1024];
__device__ __half g_h1l[50000 * 1024];
__device__ __half g_h2h[50000 * 256];
__device__ __half g_h2l[50000 * 256];
__device__ __half g_w1c[1024 * 1024];
__device__ __half g_w1t[768 * 768];
__device__ __half g_w2c[256 * 1024];
__device__ __half g_w2t[256 * 768];
__device__ __half g_w3c[64 * 256];
__device__ __half g_w3t[64 * 256];
__device__ float g_cemb[50000 * 64];
__device__ float g_temb[50000 * 64];
__device__ float g_cfemb[50000 * 64];
__device__ float g_fused[50000 * 64];    // per-unique-item attention output

// compaction state
__device__ int g_flag[NBLK_SCAN * 256];
__device__ int g_remap[NBLK_SCAN * 256]; // original -> compact
__device__ int g_items[NBLK_SCAN * 256]; // compact -> original
__device__ int g_bsum[256];
__device__ int g_boff[256];
__device__ int g_count[1];

// ------------------------- small PTX helpers --------------------------------
__device__ __forceinline__ void cp16(uint32_t dst, const void* src, int sz) {
    asm volatile("cp.async.cg.shared.global [%0], [%1], 16, %2;"
                 :: "r"(dst), "l"(src), "r"(sz));
}
__device__ __forceinline__ void ldm4(uint32_t& r0, uint32_t& r1,
                                     uint32_t& r2, uint32_t& r3, uint32_t a) {
    asm volatile("ldmatrix.sync.aligned.m8n8.x4.shared.b16 {%0,%1,%2,%3}, [%4];"
                 : "=r"(r0), "=r"(r1), "=r"(r2), "=r"(r3) : "r"(a));
}
__device__ __forceinline__ void mma_f16(float* c, const uint32_t* a,
                                        const uint32_t* b) {
    asm volatile(
        "mma.sync.aligned.m16n8k16.row.col.f32.f16.f16.f32 "
        "{%0,%1,%2,%3}, {%4,%5,%6,%7}, {%8,%9}, {%0,%1,%2,%3};"
        : "+f"(c[0]), "+f"(c[1]), "+f"(c[2]), "+f"(c[3])
        : "r"(a[0]), "r"(a[1]), "r"(a[2]), "r"(a[3]), "r"(b[0]), "r"(b[1]));
}

// ------------------------- compaction kernels -------------------------------
__global__ void flag_clear_kernel() {
    g_flag[blockIdx.x * 256 + threadIdx.x] = 0;
}
__global__ void mark_kernel(const int* __restrict__ seq) {
    int i = blockIdx.x * 256 + threadIdx.x;
    if (i < N_TOKENS) {
        int v = seq[i];
        if (v >= NUM_ITEM) v = 0;
        g_flag[v] = 1;                       // benign races
    }
}
__global__ void scan_p1_kernel() {           // per-block sums
    __shared__ int s[256];
    int t = threadIdx.x, b = blockIdx.x;
    int i = b * 256 + t;
    int f = (i < NUM_ITEM) ? g_flag[i] : 0;
    s[t] = f; __syncthreads();
    for (int o = 128; o > 0; o >>= 1) {
        if (t < o) s[t] += s[t + o];
        __syncthreads();
    }
    if (t == 0) g_bsum[b] = s[0];
}
__global__ void scan_p2_kernel() {           // scan of block sums (1 block)
    __shared__ int s[256];
    int t = threadIdx.x;
    int v = (t < NBLK_SCAN) ? g_bsum[t] : 0;
    s[t] = v; __syncthreads();
    for (int o = 1; o < 256; o <<= 1) {
        int x = (t >= o) ? s[t - o] : 0;
        __syncthreads();
        s[t] += x;
        __syncthreads();
    }
    if (t < NBLK_SCAN) g_boff[t] = s[t] - v;   // exclusive
    if (t == 255) g_count[0] = s[255];
}
__global__ void scan_p3_kernel() {           // per-element remap + inverse map
    __shared__ int s[256];
    int t = threadIdx.x, b = blockIdx.x;
    int i = b * 256 + t;
    int f = (i < NUM_ITEM) ? g_flag[i] : 0;
    s[t] = f; __syncthreads();
    for (int o = 1; o < 256; o <<= 1) {
        int x = (t >= o) ? s[t - o] : 0;
        __syncthreads();
        s[t] += x;
        __syncthreads();
    }
    if (f) {
        int pos = g_boff[b] + s[t] - f;
        g_remap[i] = pos;
        g_items[pos] = i;
    }
}

// ------------------------- fused rownorm + fp16 hi/lo split (compacted) -----
__global__ void __launch_bounds__(128)
normsplit_kernel(const float* __restrict__ X, int K,
                 __half* __restrict__ hi, __half* __restrict__ lo)
{
    const int row = blockIdx.x;
    if (!g_flag[row]) return;
    const int orow = g_remap[row];
    const float4* x4 = reinterpret_cast<const float4*>(X + (size_t)row * K);
    const int K4 = K >> 2;
    float4 v[2];
    int cnt = 0;
    float s = 0.f;
    for (int i = threadIdx.x; i < K4; i += 128) {
        float4 t = x4[i];
        v[cnt++] = t;
        s += t.x * t.x + t.y * t.y + t.z * t.z + t.w * t.w;
    }
#pragma unroll
    for (int o = 16; o > 0; o >>= 1) s += __shfl_xor_sync(0xffffffffu, s, o);
    __shared__ float red[4];
    __shared__ float s_inv;
    int w = threadIdx.x >> 5;
    if ((threadIdx.x & 31) == 0) red[w] = s;
    __syncthreads();
    if (threadIdx.x == 0) {
        float t = red[0] + red[1] + red[2] + red[3];
        s_inv = 1.0f / fmaxf(sqrtf(t), 1e-12f);
    }
    __syncthreads();
    const float inv = s_inv;
    __half2* hrow = reinterpret_cast<__half2*>(hi + (size_t)orow * K);
    __half2* lrow = reinterpret_cast<__half2*>(lo + (size_t)orow * K);
    cnt = 0;
    for (int i = threadIdx.x; i < K4; i += 128) {
        float4 t = v[cnt++];
        t.x *= inv; t.y *= inv; t.z *= inv; t.w *= inv;
        __half hx = __float2half_rn(t.x), hy = __float2half_rn(t.y);
        __half hz = __float2half_rn(t.z), hw = __float2half_rn(t.w);
        __half2 h0; h0.x = hx; h0.y = hy;
        __half2 h1; h1.x = hz; h1.y = hw;
        __half2 l0, l1;
        l0.x = __float2half_rn(t.x - __half2float(hx));
        l0.y = __float2half_rn(t.y - __half2float(hy));
        l1.x = __float2half_rn(t.z - __half2float(hz));
        l1.y = __float2half_rn(t.w - __half2float(hw));
        hrow[2 * i] = h0; hrow[2 * i + 1] = h1;
        lrow[2 * i] = l0; lrow[2 * i + 1] = l1;
    }
}

// ------------------------- fp32 -> fp16 convert (weights, hi only) ----------
__global__ void convert_kernel(const float* __restrict__ X, long n4,
                               __half* __restrict__ out)
{
    long i = blockIdx.x * (long)blockDim.x + threadIdx.x;
    if (i >= n4) return;
    float4 v = reinterpret_cast<const float4*>(X)[i];
    __half2 h0, h1;
    h0.x = __float2half_rn(v.x); h0.y = __float2half_rn(v.y);
    h1.x = __float2half_rn(v.z); h1.y = __float2half_rn(v.w);
    reinterpret_cast<__half2*>(out)[2 * i]     = h0;
    reinterpret_cast<__half2*>(out)[2 * i + 1] = h1;
}

// ------------------------- tensor-core GEMM (mma.sync fp16, 2-term) ---------
// Identical to the proven 1358us R14 configuration.
template <int BN, int WARPS_M, int WARPS_N, bool RELU, bool OUT_SPLIT>
__global__ void __launch_bounds__(256)
mma_gemm(int N, int K,
         const __half* __restrict__ Ah, const __half* __restrict__ Al,
         const __half* __restrict__ Wh,
         const float* __restrict__ bias,
         float* __restrict__ Cf,
         __half* __restrict__ Ch, __half* __restrict__ Cl)
{
    constexpr int BM = 128, BK = 32;
    constexpr int WM = BM / WARPS_M, WN = BN / WARPS_N;
    constexpr int MT = WM / 16, NT = WN / 8;
    constexpr int A_T = BM * 80;          // 80B padded rows (conflict-free)
    constexpr int W_T = BN * 80;
    constexpr int STAGE = 2 * A_T + W_T;
    constexpr int CH_A = BM * 4;          // 16B chunks per A tile
    constexpr int CH_W = BN * 4;
    constexpr int TOTAL = 2 * CH_A + CH_W;

    const int M = g_count[0];
    const int bm = blockIdx.y * BM, bn = blockIdx.x * BN;
    if (bm >= M) return;                  // compacted tail: nothing to do

    extern __shared__ char smem[];
    const uint32_t sb = (uint32_t)__cvta_generic_to_shared(smem);
    const int tid = threadIdx.x, lane = tid & 31, wid = tid >> 5;
    const int wm0 = (wid / WARPS_N) * WM;
    const int wn0 = (wid % WARPS_N) * WN;

    float acc[MT][NT][4];
#pragma unroll
    for (int m = 0; m < MT; ++m)
#pragma unroll
        for (int n = 0; n < NT; ++n)
#pragma unroll
            for (int j = 0; j < 4; ++j) acc[m][n][j] = 0.f;

    auto load_stage = [&](int s, int k0) {
        uint32_t d0 = sb + s * STAGE;
#pragma unroll
        for (int c = tid; c < TOTAL; c += 256) {
            const __half* src; uint32_t dst; int sz = 16;
            if (c < CH_A) {
                int r = c >> 2, q = c & 3, g = bm + r;
                sz = g < M ? 16 : 0; if (g >= M) g = M - 1;
                src = Ah + (size_t)g * K + k0 + q * 8;
                dst = d0 + r * 80 + q * 16;
            } else if (c < 2 * CH_A) {
                int cc = c - CH_A, r = cc >> 2, q = cc & 3, g = bm + r;
                sz = g < M ? 16 : 0; if (g >= M) g = M - 1;
                src = Al + (size_t)g * K + k0 + q * 8;
                dst = d0 + A_T + r * 80 + q * 16;
            } else {
                int cc = c - 2 * CH_A, r = cc >> 2, q = cc & 3;
                src = Wh + (size_t)(bn + r) * K + k0 + q * 8;
                dst = d0 + 2 * A_T + r * 80 + q * 16;
            }
            cp16(dst, src, sz);
        }
        asm volatile("cp.async.commit_group;");
    };

    const int nk = K / BK;
    load_stage(0, 0);

    for (int i = 0; i < nk; ++i) {
        if (i + 1 < nk) {
            load_stage((i + 1) & 1, (i + 1) * BK);
            asm volatile("cp.async.wait_group 1;");
        } else {
            asm volatile("cp.async.wait_group 0;");
        }
        __syncthreads();

        uint32_t aAh = sb + (i & 1) * STAGE;
        uint32_t aAl = aAh + A_T;
        uint32_t aWh = aAh + 2 * A_T;

#pragma unroll
        for (int kh = 0; kh < 2; ++kh) {
            uint32_t bh[NT][2];
#pragma unroll
            for (int nn = 0; nn < NT; nn += 2) {
                int r = wn0 + nn * 8 + (lane & 7) + ((lane >> 4) << 3);
                uint32_t kb = ((lane >> 3) & 1) * 16 + kh * 32;
                ldm4(bh[nn][0], bh[nn][1], bh[nn + 1][0], bh[nn + 1][1],
                     aWh + r * 80 + kb);
            }
#pragma unroll
            for (int mm = 0; mm < MT; ++mm) {
                int r = wm0 + mm * 16 + (lane & 7) + (((lane >> 3) & 1) << 3);
                uint32_t kb = ((lane >> 4) << 4) + kh * 32;
                uint32_t ah[4], al[4];
                ldm4(ah[0], ah[1], ah[2], ah[3], aAh + r * 80 + kb);
                ldm4(al[0], al[1], al[2], al[3], aAl + r * 80 + kb);
                // term-major: consecutive MMAs hit different accumulators
#pragma unroll
                for (int nn = 0; nn < NT; ++nn) mma_f16(acc[mm][nn], ah, bh[nn]);
#pragma unroll
                for (int nn = 0; nn < NT; ++nn) mma_f16(acc[mm][nn], al, bh[nn]);
            }
        }
        __syncthreads();
    }

    // epilogue
#pragma unroll
    for (int mm = 0; mm < MT; ++mm) {
#pragma unroll
        for (int nn = 0; nn < NT; ++nn) {
            int col = bn + wn0 + nn * 8 + (lane & 3) * 2;
            float b0 = __ldg(bias + col), b1 = __ldg(bias + col + 1);
#pragma unroll
            for (int h = 0; h < 2; ++h) {
                int row = bm + wm0 + mm * 16 + (lane >> 2) + h * 8;
                if (row < M) {
                    float r0 = acc[mm][nn][2 * h + 0] + b0;
                    float r1 = acc[mm][nn][2 * h + 1] + b1;
                    if (RELU) { r0 = fmaxf(r0, 0.f); r1 = fmaxf(r1, 0.f); }
                    if (OUT_SPLIT) {
                        __half h0 = __float2half_rn(r0);
                        __half h1 = __float2half_rn(r1);
                        __half l0 = __float2half_rn(r0 - __half2float(h0));
                        __half l1 = __float2half_rn(r1 - __half2float(h1));
                        __half2 vh; vh.x = h0; vh.y = h1;
                        __half2 vl; vl.x = l0; vl.y = l1;
                        *reinterpret_cast<__half2*>(&Ch[(size_t)row * N + col]) = vh;
                        *reinterpret_cast<__half2*>(&Cl[(size_t)row * N + col]) = vl;
                    } else {
                        *reinterpret_cast<float2*>(&Cf[(size_t)row * N + col]) =
                            make_float2(r0, r1);
                    }
                }
            }
        }
    }
}

// ------------------------- small SIMT GEMM (cf layer only) ------------------
template <int BM, int BN, int BK, int TM, int TN>
__global__ void __launch_bounds__((BM / TM) * (BN / TN))
sgemm_nt(int M, int N, int K,
         const float* __restrict__ A,
         const float* __restrict__ W,
         const float* __restrict__ bias,
         float* __restrict__ C)
{
    constexpr int NT = (BM / TM) * (BN / TN);
    constexpr int KQ = BK / 4;
    __shared__ float As[BK][BM];
    __shared__ float Ws[BK][BN];

    const int tid  = threadIdx.x;
    const int bm   = blockIdx.y * BM;
    const int bn   = blockIdx.x * BN;
    const int row0 = (tid / (BN / TN)) * TM;
    const int col0 = (tid % (BN / TN)) * TN;

    float acc[TM][TN];
#pragma unroll
    for (int i = 0; i < TM; ++i)
#pragma unroll
        for (int j = 0; j < TN; ++j) acc[i][j] = 0.f;

    for (int k0 = 0; k0 < K; k0 += BK) {
        for (int i = tid; i < BM * KQ; i += NT) {
            int r = i / KQ, q = i % KQ;
            int gr = bm + r;
            float4 v = make_float4(0.f, 0.f, 0.f, 0.f);
            if (gr < M)
                v = *reinterpret_cast<const float4*>(&A[(size_t)gr * K + k0 + 4 * q]);
            As[4 * q + 0][r] = v.x; As[4 * q + 1][r] = v.y;
            As[4 * q + 2][r] = v.z; As[4 * q + 3][r] = v.w;
        }
        for (int i = tid; i < BN * KQ; i += NT) {
            int r = i / KQ, q = i % KQ;
            int gr = bn + r;
            float4 v = make_float4(0.f, 0.f, 0.f, 0.f);
            if (gr < N)
                v = *reinterpret_cast<const float4*>(&W[(size_t)gr * K + k0 + 4 * q]);
            Ws[4 * q + 0][r] = v.x; Ws[4 * q + 1][r] = v.y;
            Ws[4 * q + 2][r] = v.z; Ws[4 * q + 3][r] = v.w;
        }
        __syncthreads();
#pragma unroll
        for (int k = 0; k < BK; ++k) {
            float ra[TM], rw[TN];
#pragma unroll
            for (int i = 0; i < TM; i += 4) {
                float4 v = *reinterpret_cast<const float4*>(&As[k][row0 + i]);
                ra[i] = v.x; ra[i + 1] = v.y; ra[i + 2] = v.z; ra[i + 3] = v.w;
            }
#pragma unroll
            for (int j = 0; j < TN; j += 4) {
                float4 v = *reinterpret_cast<const float4*>(&Ws[k][col0 + j]);
                rw[j] = v.x; rw[j + 1] = v.y; rw[j + 2] = v.z; rw[j + 3] = v.w;
            }
#pragma unroll
            for (int i = 0; i < TM; ++i)
#pragma unroll
                for (int j = 0; j < TN; ++j)
                    acc[i][j] = fmaf(ra[i], rw[j], acc[i][j]);
        }
        __syncthreads();
    }

#pragma unroll
    for (int i = 0; i < TM; ++i) {
        int gr = bm + row0 + i;
        if (gr < M) {
#pragma unroll
            for (int j = 0; j < TN; ++j) {
                int gc = bn + col0 + j;
                if (gc < N)
                    C[(size_t)gr * N + gc] = acc[i][j] + bias[gc];
            }
        }
    }
}

// ------------------------- attention: per unique item -----------------------
// Warp processes 4 compact item positions at a time; writes g_fused[pos].
#define ATTN_TOK_ITERS 8                 // 4 warps * 4 items * 8 = 128 items/block
#define ATTN_SMEM_FLOATS (3 * 4096 + 4 * 4 * 4 * 64)
#define ATTN_SMEM_BYTES  (ATTN_SMEM_FLOATS * 4)

__global__ void __launch_bounds__(128)
attn_kernel(const float* __restrict__ cemb,     // compacted
            const float* __restrict__ temb,     // compacted
            const float* __restrict__ cfemb,    // full catalog
            const float* __restrict__ idemb,    // full catalog
            const float* __restrict__ wq,
            const float* __restrict__ wk,
            const float* __restrict__ wv,
            float* __restrict__ fused)          // [count][64] per-item output
{
    const int count = g_count[0];
    if (blockIdx.x * 128 >= count) return;

    extern __shared__ float dyn[];
    float* w_s = dyn;                               // [3][64][64] transposed
    const int t = threadIdx.x;
    const int warp = t >> 5, lane = t & 31;
    float* xnw = dyn + 3 * 4096 + warp * 1024;      // [4 item][4 modal][64]

    for (int i = t; i < 4096; i += 128) {
        int j = i >> 6, d = i & 63;
        w_s[0 * 4096 + d * 64 + j] = wq[i];
        w_s[1 * 4096 + d * 64 + j] = wk[i];
        w_s[2 * 4096 + d * 64 + j] = wv[i];
    }
    __syncthreads();

    const float* wqs = w_s;
    const float* wks = w_s + 4096;
    const float* wvs = w_s + 2 * 4096;

    for (int it = 0; it < ATTN_TOK_ITERS; ++it) {
        const int p0 = (blockIdx.x * 4 + warp) * (4 * ATTN_TOK_ITERS) + it * 4;
        if (p0 >= count) break;

        int pos[4], orig[4];
#pragma unroll
        for (int tt = 0; tt < 4; ++tt) {
            int p = p0 + tt;
            pos[tt] = (p < count) ? p : 0;
            orig[tt] = __ldg(&g_items[pos[tt]]);
        }

        // ---- gather + l2norm + LayerNorm for 16 (item, modal) pairs
#pragma unroll
        for (int tm = 0; tm < 16; ++tm) {
            int tt = tm >> 2, m = tm & 3;
            const float* src =
                (m == 0) ? cemb + (size_t)pos[tt] * 64 :
                (m == 1) ? temb + (size_t)pos[tt] * 64 :
                (m == 2) ? cfemb + (size_t)orig[tt] * 64 :
                           idemb + (size_t)orig[tt] * 64;
            float2 e = *reinterpret_cast<const float2*>(src + 2 * lane);
            float ss = fmaf(e.x, e.x, e.y * e.y);
            float sm = e.x + e.y;
#pragma unroll
            for (int o = 16; o > 0; o >>= 1) {
                ss += __shfl_xor_sync(~0u, ss, o);
                sm += __shfl_xor_sync(~0u, sm, o);
            }
            float s  = 1.0f / fmaxf(sqrtf(ss), 1e-12f);
            float mu = s * sm * (1.0f / 64.0f);
            float var = s * s * ss * (1.0f / 64.0f) - mu * mu;
            float inv = 1.0f / sqrtf(var + 1e-5f);
            float d0 = (s * e.x - mu) * inv;
            float d1 = (s * e.y - mu) * inv;
            *reinterpret_cast<float2*>(&xnw[tm * 64 + 2 * lane]) =
                make_float2(d0, d1);
        }
        __syncwarp();

        // ---- q, k for all 16 (t,m): lane owns columns lane and lane+32
        float q0[16], q1[16], k0[16], k1[16];
#pragma unroll
        for (int tm = 0; tm < 16; ++tm) { q0[tm] = q1[tm] = k0[tm] = k1[tm] = 0.f; }
        for (int d = 0; d < 64; ++d) {
            float wqa = wqs[d * 64 + lane], wqb = wqs[d * 64 + lane + 32];
            float wka = wks[d * 64 + lane], wkb = wks[d * 64 + lane + 32];
#pragma unroll
            for (int tm = 0; tm < 16; ++tm) {
                float xv = xnw[tm * 64 + d];
                q0[tm] = fmaf(xv, wqa, q0[tm]);
                q1[tm] = fmaf(xv, wqb, q1[tm]);
                k0[tm] = fmaf(xv, wka, k0[tm]);
                k1[tm] = fmaf(xv, wkb, k1[tm]);
            }
        }

        // ---- scores + softmax -> pooled coefficients c[t][n]
        float cc[4][4];
#pragma unroll
        for (int tt = 0; tt < 4; ++tt) {
            float sc[4][4];
#pragma unroll
            for (int m = 0; m < 4; ++m)
#pragma unroll
                for (int n = 0; n < 4; ++n) {
                    float p = fmaf(q0[tt * 4 + m], k0[tt * 4 + n],
                                   q1[tt * 4 + m] * k1[tt * 4 + n]);
#pragma unroll
                    for (int o = 16; o > 0; o >>= 1) p += __shfl_xor_sync(~0u, p, o);
                    sc[m][n] = p * 0.125f;
                }
            float c0 = 0.f, c1 = 0.f, c2 = 0.f, c3 = 0.f;
#pragma unroll
            for (int m = 0; m < 4; ++m) {
                float mx = fmaxf(fmaxf(sc[m][0], sc[m][1]),
                                 fmaxf(sc[m][2], sc[m][3]));
                float e0 = expf(sc[m][0] - mx), e1 = expf(sc[m][1] - mx);
                float e2 = expf(sc[m][2] - mx), e3 = expf(sc[m][3] - mx);
                float rd = 1.0f / (e0 + e1 + e2 + e3);
                c0 = fmaf(e0, rd, c0); c1 = fmaf(e1, rd, c1);
                c2 = fmaf(e2, rd, c2); c3 = fmaf(e3, rd, c3);
            }
            cc[tt][0] = 0.25f * c0; cc[tt][1] = 0.25f * c1;
            cc[tt][2] = 0.25f * c2; cc[tt][3] = 0.25f * c3;
        }

        // ---- fused[p] = (sum_n c_n * xn_n) @ wv^T  (cols lane, lane+32)
        float o0[4] = {0.f, 0.f, 0.f, 0.f}, o1[4] = {0.f, 0.f, 0.f, 0.f};
        for (int d = 0; d < 64; ++d) {
            float wva = wvs[d * 64 + lane], wvb = wvs[d * 64 + lane + 32];
#pragma unroll
            for (int tt = 0; tt < 4; ++tt) {
                float z = fmaf(cc[tt][0], xnw[(tt * 4 + 0) * 64 + d],
                          fmaf(cc[tt][1], xnw[(tt * 4 + 1) * 64 + d],
                          fmaf(cc[tt][2], xnw[(tt * 4 + 2) * 64 + d],
                               cc[tt][3] * xnw[(tt * 4 + 3) * 64 + d])));
                o0[tt] = fmaf(z, wva, o0[tt]);
                o1[tt] = fmaf(z, wvb, o1[tt]);
            }
        }
#pragma unroll
        for (int tt = 0; tt < 4; ++tt) {
            if (p0 + tt < count) {
                fused[(size_t)(p0 + tt) * 64 + lane]      = o0[tt];
                fused[(size_t)(p0 + tt) * 64 + lane + 32] = o1[tt];
            }
        }
        __syncwarp();
    }
}

// ------------------------- scatter: token -> fused[remap[item]] -------------
__global__ void __launch_bounds__(256)
scatter_kernel(const int* __restrict__ seq,
               const float* __restrict__ fused,
               float* __restrict__ out)
{
    // one thread per float4: 51200 tokens * 16 float4
    int i = blockIdx.x * 256 + threadIdx.x;
    if (i >= N_TOKENS * 16) return;
    int tok = i >> 4, c4 = i & 15;
    int v = __ldg(&seq[tok]);
    if (v >= NUM_ITEM) v = 0;
    int pos = __ldg(&g_remap[v]);
    reinterpret_cast<float4*>(out)[(size_t)tok * 16 + c4] =
        __ldg(&reinterpret_cast<const float4*>(fused)[(size_t)pos * 16 + c4]);
}

// ------------------------- launch ------------------------------------------
static inline int grid4(long n4) { return (int)((n4 + 255) / 256); }

extern "C" void kernel_launch(void* const* d_in, const int* in_sizes, int n_in,
                              void* d_out, int out_size)
{
    const int*   seq     = (const int*)d_in[0];
    const float* content = (const float*)d_in[1];
    const float* text    = (const float*)d_in[2];
    const float* cff     = (const float*)d_in[3];
    const float* idemb   = (const float*)d_in[4];
    const float* c_w1 = (const float*)d_in[5],  *c_b1 = (const float*)d_in[6];
    const float* c_w2 = (const float*)d_in[7],  *c_b2 = (const float*)d_in[8];
    const float* c_w3 = (const float*)d_in[9],  *c_b3 = (const float*)d_in[10];
    const float* t_w1 = (const float*)d_in[11], *t_b1 = (const float*)d_in[12];
    const float* t_w2 = (const float*)d_in[13], *t_b2 = (const float*)d_in[14];
    const float* t_w3 = (const float*)d_in[15], *t_b3 = (const float*)d_in[16];
    const float* cf_w = (const float*)d_in[17], *cf_b = (const float*)d_in[18];
    const float* wq   = (const float*)d_in[19];
    const float* wk   = (const float*)d_in[20];
    const float* wv   = (const float*)d_in[21];
    float* out = (float*)d_out;

    __half *ahc, *alc, *aht, *alt, *h1h, *h1l, *h2h, *h2l;
    __half *w1c, *w1t, *w2c, *w2t, *w3c, *w3t;
    float *cemb, *temb, *cfemb, *fused;
    cudaGetSymbolAddress((void**)&ahc, g_ahc);  cudaGetSymbolAddress((void**)&alc, g_alc);
    cudaGetSymbolAddress((void**)&aht, g_aht);  cudaGetSymbolAddress((void**)&alt, g_alt);
    cudaGetSymbolAddress((void**)&h1h, g_h1h);  cudaGetSymbolAddress((void**)&h1l, g_h1l);
    cudaGetSymbolAddress((void**)&h2h, g_h2h);  cudaGetSymbolAddress((void**)&h2l, g_h2l);
    cudaGetSymbolAddress((void**)&w1c, g_w1c);  cudaGetSymbolAddress((void**)&w1t, g_w1t);
    cudaGetSymbolAddress((void**)&w2c, g_w2c);  cudaGetSymbolAddress((void**)&w2t, g_w2t);
    cudaGetSymbolAddress((void**)&w3c, g_w3c);  cudaGetSymbolAddress((void**)&w3t, g_w3t);
    cudaGetSymbolAddress((void**)&cemb,  g_cemb);
    cudaGetSymbolAddress((void**)&temb,  g_temb);
    cudaGetSymbolAddress((void**)&cfemb, g_cfemb);
    cudaGetSymbolAddress((void**)&fused, g_fused);

    const int gy = (NUM_ITEM + 127) / 128;   // 391 (worst-case M)

    const int SMEM_BN128 = 2 * (2 * 128 * 80 + 128 * 80);   // 61440
    const int SMEM_BN64  = 2 * (2 * 128 * 80 + 64 * 80);    // 51200
    cudaFuncSetAttribute((const void*)mma_gemm<128, 2, 4, true, true>,
                         cudaFuncAttributeMaxDynamicSharedMemorySize, SMEM_BN128);
    cudaFuncSetAttribute((const void*)mma_gemm<64, 4, 2, false, false>,
                         cudaFuncAttributeMaxDynamicSharedMemorySize, SMEM_BN64);
    cudaFuncSetAttribute(attn_kernel,
                         cudaFuncAttributeMaxDynamicSharedMemorySize, ATTN_SMEM_BYTES);

    // ---------------- compaction ----------------
    flag_clear_kernel<<<NBLK_SCAN, 256>>>();
    mark_kernel<<<(N_TOKENS + 255) / 256, 256>>>(seq);
    scan_p1_kernel<<<NBLK_SCAN, 256>>>();
    scan_p2_kernel<<<1, 256>>>();
    scan_p3_kernel<<<NBLK_SCAN, 256>>>();

    // ---------------- normsplits (compacted) + weight converts --------------
    normsplit_kernel<<<NUM_ITEM, 128>>>(content, 1024, ahc, alc);
    normsplit_kernel<<<NUM_ITEM, 128>>>(text, 768, aht, alt);
    convert_kernel<<<grid4(1024L * 1024 / 4), 256>>>(c_w1, 1024L * 1024 / 4, w1c);
    convert_kernel<<<grid4(256L * 1024 / 4), 256>>>(c_w2, 256L * 1024 / 4, w2c);
    convert_kernel<<<grid4(64L * 256 / 4), 256>>>(c_w3, 64L * 256 / 4, w3c);
    convert_kernel<<<grid4(768L * 768 / 4), 256>>>(t_w1, 768L * 768 / 4, w1t);
    convert_kernel<<<grid4(256L * 768 / 4), 256>>>(t_w2, 256L * 768 / 4, w2t);
    convert_kernel<<<grid4(64L * 256 / 4), 256>>>(t_w3, 64L * 256 / 4, w3t);

    // ---------------- content branch (M = g_count at runtime) ----------------
    mma_gemm<128, 2, 4, true, true><<<dim3(8, gy), 256, SMEM_BN128>>>(
        1024, 1024, ahc, alc, w1c, c_b1, nullptr, h1h, h1l);
    mma_gemm<128, 2, 4, true, true><<<dim3(2, gy), 256, SMEM_BN128>>>(
        256, 1024, h1h, h1l, w2c, c_b2, nullptr, h2h, h2l);
    mma_gemm<64, 4, 2, false, false><<<dim3(1, gy), 256, SMEM_BN64>>>(
        64, 256, h2h, h2l, w3c, c_b3, cemb, nullptr, nullptr);

    // ---------------- text branch ----------------
    mma_gemm<128, 2, 4, true, true><<<dim3(6, gy), 256, SMEM_BN128>>>(
        768, 768, aht, alt, w1t, t_b1, nullptr, h1h, h1l);
    mma_gemm<128, 2, 4, true, true><<<dim3(2, gy), 256, SMEM_BN128>>>(
        256, 768, h1h, h1l, w2t, t_b2, nullptr, h2h, h2l);
    mma_gemm<64, 4, 2, false, false><<<dim3(1, gy), 256, SMEM_BN64>>>(
        64, 256, h2h, h2l, w3t, t_b3, temb, nullptr, nullptr);

    // cf linear (tiny, full catalog)
    sgemm_nt<128, 64, 16, 8, 4><<<dim3(1, gy), 256>>>(
        NUM_ITEM, 64, 64, cff, cf_w, cf_b, cfemb);

    // per-unique-item attention, then scatter to tokens
    attn_kernel<<<gy, 128, ATTN_SMEM_BYTES>>>(
        cemb, temb, cfemb, idemb, wq, wk, wv, fused);
    scatter_kernel<<<(N_TOKENS * 16 + 255) / 256, 256>>>(seq, fused, out);
}

// round 17
// speedup vs baseline: 1.5217x; 1.0824x over previous
#include <cuda_runtime.h>
#include <cuda_fp16.h>
#include <stdint.h>
#include <math.h>

// ---------------------------------------------------------------------------
// DisentangledHierarchicalEncoder — fp16 2-term GEMMs + compaction + per-item
// attention dedup. This round: isolated 2-CTA/SM occupancy test on the proven
// GEMM tiling, plus compacted cf linear (exact).
// ---------------------------------------------------------------------------

#define NUM_ITEM   50000
#define N_TOKENS   (1024 * 50)
#define NBLK_SCAN  196                   // 196*256 = 50176 >= NUM_ITEM+1

// ------------------------- device scratch (static) -------------------------
__device__ __half g_ahc[50000 * 1024];
__device__ __half g_alc[50000 * 1024];
__device__ __half g_aht[50000 * 768];
__device__ __half g_alt[50000 * 768];
__device__ __half g_h1h[50000 * 1024];
__device__ __half g_h1l[50000 * 1024];
__device__ __half g_h2h[50000 * 256];
__device__ __half g_h2l[50000 * 256];
__device__ __half g_w1c[1024 * 1024];
__device__ __half g_w1t[768 * 768];
__device__ __half g_w2c[256 * 1024];
__device__ __half g_w2t[256 * 768];
__device__ __half g_w3c[64 * 256];
__device__ __half g_w3t[64 * 256];
__device__ float g_cemb[50000 * 64];
__device__ float g_temb[50000 * 64];
__device__ float g_cfemb[50000 * 64];    // compacted (by pos)
__device__ float g_fused[50000 * 64];    // per-unique-item attention output

// compaction state
__device__ int g_flag[NBLK_SCAN * 256];
__device__ int g_remap[NBLK_SCAN * 256]; // original -> compact
__device__ int g_items[NBLK_SCAN * 256]; // compact -> original
__device__ int g_bsum[256];
__device__ int g_boff[256];
__device__ int g_count[1];

// ------------------------- small PTX helpers --------------------------------
__device__ __forceinline__ void cp16(uint32_t dst, const void* src, int sz) {
    asm volatile("cp.async.cg.shared.global [%0], [%1], 16, %2;"
                 :: "r"(dst), "l"(src), "r"(sz));
}
__device__ __forceinline__ void ldm4(uint32_t& r0, uint32_t& r1,
                                     uint32_t& r2, uint32_t& r3, uint32_t a) {
    asm volatile("ldmatrix.sync.aligned.m8n8.x4.shared.b16 {%0,%1,%2,%3}, [%4];"
                 : "=r"(r0), "=r"(r1), "=r"(r2), "=r"(r3) : "r"(a));
}
__device__ __forceinline__ void mma_f16(float* c, const uint32_t* a,
                                        const uint32_t* b) {
    asm volatile(
        "mma.sync.aligned.m16n8k16.row.col.f32.f16.f16.f32 "
        "{%0,%1,%2,%3}, {%4,%5,%6,%7}, {%8,%9}, {%0,%1,%2,%3};"
        : "+f"(c[0]), "+f"(c[1]), "+f"(c[2]), "+f"(c[3])
        : "r"(a[0]), "r"(a[1]), "r"(a[2]), "r"(a[3]), "r"(b[0]), "r"(b[1]));
}

// ------------------------- compaction kernels -------------------------------
__global__ void flag_clear_kernel() {
    g_flag[blockIdx.x * 256 + threadIdx.x] = 0;
}
__global__ void mark_kernel(const int* __restrict__ seq) {
    int i = blockIdx.x * 256 + threadIdx.x;
    if (i < N_TOKENS) {
        int v = seq[i];
        if (v >= NUM_ITEM) v = 0;
        g_flag[v] = 1;                       // benign races
    }
}
__global__ void scan_p1_kernel() {           // per-block sums
    __shared__ int s[256];
    int t = threadIdx.x, b = blockIdx.x;
    int i = b * 256 + t;
    int f = (i < NUM_ITEM) ? g_flag[i] : 0;
    s[t] = f; __syncthreads();
    for (int o = 128; o > 0; o >>= 1) {
        if (t < o) s[t] += s[t + o];
        __syncthreads();
    }
    if (t == 0) g_bsum[b] = s[0];
}
__global__ void scan_p2_kernel() {           // scan of block sums (1 block)
    __shared__ int s[256];
    int t = threadIdx.x;
    int v = (t < NBLK_SCAN) ? g_bsum[t] : 0;
    s[t] = v; __syncthreads();
    for (int o = 1; o < 256; o <<= 1) {
        int x = (t >= o) ? s[t - o] : 0;
        __syncthreads();
        s[t] += x;
        __syncthreads();
    }
    if (t < NBLK_SCAN) g_boff[t] = s[t] - v;   // exclusive
    if (t == 255) g_count[0] = s[255];
}
__global__ void scan_p3_kernel() {           // per-element remap + inverse map
    __shared__ int s[256];
    int t = threadIdx.x, b = blockIdx.x;
    int i = b * 256 + t;
    int f = (i < NUM_ITEM) ? g_flag[i] : 0;
    s[t] = f; __syncthreads();
    for (int o = 1; o < 256; o <<= 1) {
        int x = (t >= o) ? s[t - o] : 0;
        __syncthreads();
        s[t] += x;
        __syncthreads();
    }
    if (f) {
        int pos = g_boff[b] + s[t] - f;
        g_remap[i] = pos;
        g_items[pos] = i;
    }
}

// ------------------------- fused rownorm + fp16 hi/lo split (compacted) -----
__global__ void __launch_bounds__(128)
normsplit_kernel(const float* __restrict__ X, int K,
                 __half* __restrict__ hi, __half* __restrict__ lo)
{
    const int row = blockIdx.x;
    if (!g_flag[row]) return;
    const int orow = g_remap[row];
    const float4* x4 = reinterpret_cast<const float4*>(X + (size_t)row * K);
    const int K4 = K >> 2;
    float4 v[2];
    int cnt = 0;
    float s = 0.f;
    for (int i = threadIdx.x; i < K4; i += 128) {
        float4 t = x4[i];
        v[cnt++] = t;
        s += t.x * t.x + t.y * t.y + t.z * t.z + t.w * t.w;
    }
#pragma unroll
    for (int o = 16; o > 0; o >>= 1) s += __shfl_xor_sync(0xffffffffu, s, o);
    __shared__ float red[4];
    __shared__ float s_inv;
    int w = threadIdx.x >> 5;
    if ((threadIdx.x & 31) == 0) red[w] = s;
    __syncthreads();
    if (threadIdx.x == 0) {
        float t = red[0] + red[1] + red[2] + red[3];
        s_inv = 1.0f / fmaxf(sqrtf(t), 1e-12f);
    }
    __syncthreads();
    const float inv = s_inv;
    __half2* hrow = reinterpret_cast<__half2*>(hi + (size_t)orow * K);
    __half2* lrow = reinterpret_cast<__half2*>(lo + (size_t)orow * K);
    cnt = 0;
    for (int i = threadIdx.x; i < K4; i += 128) {
        float4 t = v[cnt++];
        t.x *= inv; t.y *= inv; t.z *= inv; t.w *= inv;
        __half hx = __float2half_rn(t.x), hy = __float2half_rn(t.y);
        __half hz = __float2half_rn(t.z), hw = __float2half_rn(t.w);
        __half2 h0; h0.x = hx; h0.y = hy;
        __half2 h1; h1.x = hz; h1.y = hw;
        __half2 l0, l1;
        l0.x = __float2half_rn(t.x - __half2float(hx));
        l0.y = __float2half_rn(t.y - __half2float(hy));
        l1.x = __float2half_rn(t.z - __half2float(hz));
        l1.y = __float2half_rn(t.w - __half2float(hw));
        hrow[2 * i] = h0; hrow[2 * i + 1] = h1;
        lrow[2 * i] = l0; lrow[2 * i + 1] = l1;
    }
}

// ------------------------- fp32 -> fp16 convert (weights, hi only) ----------
__global__ void convert_kernel(const float* __restrict__ X, long n4,
                               __half* __restrict__ out)
{
    long i = blockIdx.x * (long)blockDim.x + threadIdx.x;
    if (i >= n4) return;
    float4 v = reinterpret_cast<const float4*>(X)[i];
    __half2 h0, h1;
    h0.x = __float2half_rn(v.x); h0.y = __float2half_rn(v.y);
    h1.x = __float2half_rn(v.z); h1.y = __float2half_rn(v.w);
    reinterpret_cast<__half2*>(out)[2 * i]     = h0;
    reinterpret_cast<__half2*>(out)[2 * i + 1] = h1;
}

// ------------------------- tensor-core GEMM (mma.sync fp16, 2-term) ---------
// Proven R14/R15 tiling; ONLY change this round: min-blocks 2 (occupancy).
template <int BN, int WARPS_M, int WARPS_N, bool RELU, bool OUT_SPLIT>
__global__ void __launch_bounds__(256, 2)
mma_gemm(int N, int K,
         const __half* __restrict__ Ah, const __half* __restrict__ Al,
         const __half* __restrict__ Wh,
         const float* __restrict__ bias,
         float* __restrict__ Cf,
         __half* __restrict__ Ch, __half* __restrict__ Cl)
{
    constexpr int BM = 128, BK = 32;
    constexpr int WM = BM / WARPS_M, WN = BN / WARPS_N;
    constexpr int MT = WM / 16, NT = WN / 8;
    constexpr int A_T = BM * 80;          // 80B padded rows (conflict-free)
    constexpr int W_T = BN * 80;
    constexpr int STAGE = 2 * A_T + W_T;
    constexpr int CH_A = BM * 4;          // 16B chunks per A tile
    constexpr int CH_W = BN * 4;
    constexpr int TOTAL = 2 * CH_A + CH_W;

    const int M = g_count[0];
    const int bm = blockIdx.y * BM, bn = blockIdx.x * BN;
    if (bm >= M) return;                  // compacted tail: nothing to do

    extern __shared__ char smem[];
    const uint32_t sb = (uint32_t)__cvta_generic_to_shared(smem);
    const int tid = threadIdx.x, lane = tid & 31, wid = tid >> 5;
    const int wm0 = (wid / WARPS_N) * WM;
    const int wn0 = (wid % WARPS_N) * WN;

    float acc[MT][NT][4];
#pragma unroll
    for (int m = 0; m < MT; ++m)
#pragma unroll
        for (int n = 0; n < NT; ++n)
#pragma unroll
            for (int j = 0; j < 4; ++j) acc[m][n][j] = 0.f;

    auto load_stage = [&](int s, int k0) {
        uint32_t d0 = sb + s * STAGE;
#pragma unroll
        for (int c = tid; c < TOTAL; c += 256) {
            const __half* src; uint32_t dst; int sz = 16;
            if (c < CH_A) {
                int r = c >> 2, q = c & 3, g = bm + r;
                sz = g < M ? 16 : 0; if (g >= M) g = M - 1;
                src = Ah + (size_t)g * K + k0 + q * 8;
                dst = d0 + r * 80 + q * 16;
            } else if (c < 2 * CH_A) {
                int cc = c - CH_A, r = cc >> 2, q = cc & 3, g = bm + r;
                sz = g < M ? 16 : 0; if (g >= M) g = M - 1;
                src = Al + (size_t)g * K + k0 + q * 8;
                dst = d0 + A_T + r * 80 + q * 16;
            } else {
                int cc = c - 2 * CH_A, r = cc >> 2, q = cc & 3;
                src = Wh + (size_t)(bn + r) * K + k0 + q * 8;
                dst = d0 + 2 * A_T + r * 80 + q * 16;
            }
            cp16(dst, src, sz);
        }
        asm volatile("cp.async.commit_group;");
    };

    const int nk = K / BK;
    load_stage(0, 0);

    for (int i = 0; i < nk; ++i) {
        if (i + 1 < nk) {
            load_stage((i + 1) & 1, (i + 1) * BK);
            asm volatile("cp.async.wait_group 1;");
        } else {
            asm volatile("cp.async.wait_group 0;");
        }
        __syncthreads();

        uint32_t aAh = sb + (i & 1) * STAGE;
        uint32_t aAl = aAh + A_T;
        uint32_t aWh = aAh + 2 * A_T;

#pragma unroll
        for (int kh = 0; kh < 2; ++kh) {
            uint32_t bh[NT][2];
#pragma unroll
            for (int nn = 0; nn < NT; nn += 2) {
                int r = wn0 + nn * 8 + (lane & 7) + ((lane >> 4) << 3);
                uint32_t kb = ((lane >> 3) & 1) * 16 + kh * 32;
                ldm4(bh[nn][0], bh[nn][1], bh[nn + 1][0], bh[nn + 1][1],
                     aWh + r * 80 + kb);
            }
#pragma unroll
            for (int mm = 0; mm < MT; ++mm) {
                int r = wm0 + mm * 16 + (lane & 7) + (((lane >> 3) & 1) << 3);
                uint32_t kb = ((lane >> 4) << 4) + kh * 32;
                uint32_t ah[4], al[4];
                ldm4(ah[0], ah[1], ah[2], ah[3], aAh + r * 80 + kb);
                ldm4(al[0], al[1], al[2], al[3], aAl + r * 80 + kb);
                // term-major: consecutive MMAs hit different accumulators
#pragma unroll
                for (int nn = 0; nn < NT; ++nn) mma_f16(acc[mm][nn], ah, bh[nn]);
#pragma unroll
                for (int nn = 0; nn < NT; ++nn) mma_f16(acc[mm][nn], al, bh[nn]);
            }
        }
        __syncthreads();
    }

    // epilogue
#pragma unroll
    for (int mm = 0; mm < MT; ++mm) {
#pragma unroll
        for (int nn = 0; nn < NT; ++nn) {
            int col = bn + wn0 + nn * 8 + (lane & 3) * 2;
            float b0 = __ldg(bias + col), b1 = __ldg(bias + col + 1);
#pragma unroll
            for (int h = 0; h < 2; ++h) {
                int row = bm + wm0 + mm * 16 + (lane >> 2) + h * 8;
                if (row < M) {
                    float r0 = acc[mm][nn][2 * h + 0] + b0;
                    float r1 = acc[mm][nn][2 * h + 1] + b1;
                    if (RELU) { r0 = fmaxf(r0, 0.f); r1 = fmaxf(r1, 0.f); }
                    if (OUT_SPLIT) {
                        __half h0 = __float2half_rn(r0);
                        __half h1 = __float2half_rn(r1);
                        __half l0 = __float2half_rn(r0 - __half2float(h0));
                        __half l1 = __float2half_rn(r1 - __half2float(h1));
                        __half2 vh; vh.x = h0; vh.y = h1;
                        __half2 vl; vl.x = l0; vl.y = l1;
                        *reinterpret_cast<__half2*>(&Ch[(size_t)row * N + col]) = vh;
                        *reinterpret_cast<__half2*>(&Cl[(size_t)row * N + col]) = vl;
                    } else {
                        *reinterpret_cast<float2*>(&Cf[(size_t)row * N + col]) =
                            make_float2(r0, r1);
                    }
                }
            }
        }
    }
}

// ------------------------- small SIMT GEMM (cf layer, compacted rows) -------
// A rows gathered via g_items (compact pos -> original row); C written at pos.
template <int BM, int BN, int BK, int TM, int TN>
__global__ void __launch_bounds__((BM / TM) * (BN / TN))
sgemm_nt_gather(int N, int K,
                const float* __restrict__ A,
                const float* __restrict__ W,
                const float* __restrict__ bias,
                float* __restrict__ C)
{
    constexpr int NT = (BM / TM) * (BN / TN);
    constexpr int KQ = BK / 4;
    __shared__ float As[BK][BM];
    __shared__ float Ws[BK][BN];

    const int M = g_count[0];
    const int bm = blockIdx.y * BM;
    if (bm >= M) return;
    const int bn = blockIdx.x * BN;

    const int tid  = threadIdx.x;
    const int row0 = (tid / (BN / TN)) * TM;
    const int col0 = (tid % (BN / TN)) * TN;

    float acc[TM][TN];
#pragma unroll
    for (int i = 0; i < TM; ++i)
#pragma unroll
        for (int j = 0; j < TN; ++j) acc[i][j] = 0.f;

    for (int k0 = 0; k0 < K; k0 += BK) {
        for (int i = tid; i < BM * KQ; i += NT) {
            int r = i / KQ, q = i % KQ;
            int gr = bm + r;
            float4 v = make_float4(0.f, 0.f, 0.f, 0.f);
            if (gr < M) {
                int orow = g_items[gr];
                v = *reinterpret_cast<const float4*>(&A[(size_t)orow * K + k0 + 4 * q]);
            }
            As[4 * q + 0][r] = v.x; As[4 * q + 1][r] = v.y;
            As[4 * q + 2][r] = v.z; As[4 * q + 3][r] = v.w;
        }
        for (int i = tid; i < BN * KQ; i += NT) {
            int r = i / KQ, q = i % KQ;
            int gr = bn + r;
            float4 v = make_float4(0.f, 0.f, 0.f, 0.f);
            if (gr < N)
                v = *reinterpret_cast<const float4*>(&W[(size_t)gr * K + k0 + 4 * q]);
            Ws[4 * q + 0][r] = v.x; Ws[4 * q + 1][r] = v.y;
            Ws[4 * q + 2][r] = v.z; Ws[4 * q + 3][r] = v.w;
        }
        __syncthreads();
#pragma unroll
        for (int k = 0; k < BK; ++k) {
            float ra[TM], rw[TN];
#pragma unroll
            for (int i = 0; i < TM; i += 4) {
                float4 v = *reinterpret_cast<const float4*>(&As[k][row0 + i]);
                ra[i] = v.x; ra[i + 1] = v.y; ra[i + 2] = v.z; ra[i + 3] = v.w;
            }
#pragma unroll
            for (int j = 0; j < TN; j += 4) {
                float4 v = *reinterpret_cast<const float4*>(&Ws[k][col0 + j]);
                rw[j] = v.x; rw[j + 1] = v.y; rw[j + 2] = v.z; rw[j + 3] = v.w;
            }
#pragma unroll
            for (int i = 0; i < TM; ++i)
#pragma unroll
                for (int j = 0; j < TN; ++j)
                    acc[i][j] = fmaf(ra[i], rw[j], acc[i][j]);
        }
        __syncthreads();
    }

#pragma unroll
    for (int i = 0; i < TM; ++i) {
        int gr = bm + row0 + i;
        if (gr < M) {
#pragma unroll
            for (int j = 0; j < TN; ++j) {
                int gc = bn + col0 + j;
                if (gc < N)
                    C[(size_t)gr * N + gc] = acc[i][j] + bias[gc];
            }
        }
    }
}

// ------------------------- attention: per unique item -----------------------
#define ATTN_TOK_ITERS 8                 // 4 warps * 4 items * 8 = 128 items/block
#define ATTN_SMEM_FLOATS (3 * 4096 + 4 * 4 * 4 * 64)
#define ATTN_SMEM_BYTES  (ATTN_SMEM_FLOATS * 4)

__global__ void __launch_bounds__(128)
attn_kernel(const float* __restrict__ cemb,     // compacted
            const float* __restrict__ temb,     // compacted
            const float* __restrict__ cfemb,    // compacted
            const float* __restrict__ idemb,    // full catalog
            const float* __restrict__ wq,
            const float* __restrict__ wk,
            const float* __restrict__ wv,
            float* __restrict__ fused)          // [count][64] per-item output
{
    const int count = g_count[0];
    if (blockIdx.x * 128 >= count) return;

    extern __shared__ float dyn[];
    float* w_s = dyn;                               // [3][64][64] transposed
    const int t = threadIdx.x;
    const int warp = t >> 5, lane = t & 31;
    float* xnw = dyn + 3 * 4096 + warp * 1024;      // [4 item][4 modal][64]

    for (int i = t; i < 4096; i += 128) {
        int j = i >> 6, d = i & 63;
        w_s[0 * 4096 + d * 64 + j] = wq[i];
        w_s[1 * 4096 + d * 64 + j] = wk[i];
        w_s[2 * 4096 + d * 64 + j] = wv[i];
    }
    __syncthreads();

    const float* wqs = w_s;
    const float* wks = w_s + 4096;
    const float* wvs = w_s + 2 * 4096;

    for (int it = 0; it < ATTN_TOK_ITERS; ++it) {
        const int p0 = (blockIdx.x * 4 + warp) * (4 * ATTN_TOK_ITERS) + it * 4;
        if (p0 >= count) break;

        int pos[4], orig[4];
#pragma unroll
        for (int tt = 0; tt < 4; ++tt) {
            int p = p0 + tt;
            pos[tt] = (p < count) ? p : 0;
            orig[tt] = __ldg(&g_items[pos[tt]]);
        }

        // ---- gather + l2norm + LayerNorm for 16 (item, modal) pairs
#pragma unroll
        for (int tm = 0; tm < 16; ++tm) {
            int tt = tm >> 2, m = tm & 3;
            const float* src =
                (m == 0) ? cemb + (size_t)pos[tt] * 64 :
                (m == 1) ? temb + (size_t)pos[tt] * 64 :
                (m == 2) ? cfemb + (size_t)pos[tt] * 64 :
                           idemb + (size_t)orig[tt] * 64;
            float2 e = *reinterpret_cast<const float2*>(src + 2 * lane);
            float ss = fmaf(e.x, e.x, e.y * e.y);
            float sm = e.x + e.y;
#pragma unroll
            for (int o = 16; o > 0; o >>= 1) {
                ss += __shfl_xor_sync(~0u, ss, o);
                sm += __shfl_xor_sync(~0u, sm, o);
            }
            float s  = 1.0f / fmaxf(sqrtf(ss), 1e-12f);
            float mu = s * sm * (1.0f / 64.0f);
            float var = s * s * ss * (1.0f / 64.0f) - mu * mu;
            float inv = 1.0f / sqrtf(var + 1e-5f);
            float d0 = (s * e.x - mu) * inv;
            float d1 = (s * e.y - mu) * inv;
            *reinterpret_cast<float2*>(&xnw[tm * 64 + 2 * lane]) =
                make_float2(d0, d1);
        }
        __syncwarp();

        // ---- q, k for all 16 (t,m): lane owns columns lane and lane+32
        float q0[16], q1[16], k0[16], k1[16];
#pragma unroll
        for (int tm = 0; tm < 16; ++tm) { q0[tm] = q1[tm] = k0[tm] = k1[tm] = 0.f; }
        for (int d = 0; d < 64; ++d) {
            float wqa = wqs[d * 64 + lane], wqb = wqs[d * 64 + lane + 32];
            float wka = wks[d * 64 + lane], wkb = wks[d * 64 + lane + 32];
#pragma unroll
            for (int tm = 0; tm < 16; ++tm) {
                float xv = xnw[tm * 64 + d];
                q0[tm] = fmaf(xv, wqa, q0[tm]);
                q1[tm] = fmaf(xv, wqb, q1[tm]);
                k0[tm] = fmaf(xv, wka, k0[tm]);
                k1[tm] = fmaf(xv, wkb, k1[tm]);
            }
        }

        // ---- scores + softmax -> pooled coefficients c[t][n]
        float cc[4][4];
#pragma unroll
        for (int tt = 0; tt < 4; ++tt) {
            float sc[4][4];
#pragma unroll
            for (int m = 0; m < 4; ++m)
#pragma unroll
                for (int n = 0; n < 4; ++n) {
                    float p = fmaf(q0[tt * 4 + m], k0[tt * 4 + n],
                                   q1[tt * 4 + m] * k1[tt * 4 + n]);
#pragma unroll
                    for (int o = 16; o > 0; o >>= 1) p += __shfl_xor_sync(~0u, p, o);
                    sc[m][n] = p * 0.125f;
                }
            float c0 = 0.f, c1 = 0.f, c2 = 0.f, c3 = 0.f;
#pragma unroll
            for (int m = 0; m < 4; ++m) {
                float mx = fmaxf(fmaxf(sc[m][0], sc[m][1]),
                                 fmaxf(sc[m][2], sc[m][3]));
                float e0 = expf(sc[m][0] - mx), e1 = expf(sc[m][1] - mx);
                float e2 = expf(sc[m][2] - mx), e3 = expf(sc[m][3] - mx);
                float rd = 1.0f / (e0 + e1 + e2 + e3);
                c0 = fmaf(e0, rd, c0); c1 = fmaf(e1, rd, c1);
                c2 = fmaf(e2, rd, c2); c3 = fmaf(e3, rd, c3);
            }
            cc[tt][0] = 0.25f * c0; cc[tt][1] = 0.25f * c1;
            cc[tt][2] = 0.25f * c2; cc[tt][3] = 0.25f * c3;
        }

        // ---- fused[p] = (sum_n c_n * xn_n) @ wv^T  (cols lane, lane+32)
        float o0[4] = {0.f, 0.f, 0.f, 0.f}, o1[4] = {0.f, 0.f, 0.f, 0.f};
        for (int d = 0; d < 64; ++d) {
            float wva = wvs[d * 64 + lane], wvb = wvs[d * 64 + lane + 32];
#pragma unroll
            for (int tt = 0; tt < 4; ++tt) {
                float z = fmaf(cc[tt][0], xnw[(tt * 4 + 0) * 64 + d],
                          fmaf(cc[tt][1], xnw[(tt * 4 + 1) * 64 + d],
                          fmaf(cc[tt][2], xnw[(tt * 4 + 2) * 64 + d],
                               cc[tt][3] * xnw[(tt * 4 + 3) * 64 + d])));
                o0[tt] = fmaf(z, wva, o0[tt]);
                o1[tt] = fmaf(z, wvb, o1[tt]);
            }
        }
#pragma unroll
        for (int tt = 0; tt < 4; ++tt) {
            if (p0 + tt < count) {
                fused[(size_t)(p0 + tt) * 64 + lane]      = o0[tt];
                fused[(size_t)(p0 + tt) * 64 + lane + 32] = o1[tt];
            }
        }
        __syncwarp();
    }
}

// ------------------------- scatter: token -> fused[remap[item]] -------------
__global__ void __launch_bounds__(256)
scatter_kernel(const int* __restrict__ seq,
               const float* __restrict__ fused,
               float* __restrict__ out)
{
    // one thread per float4: 51200 tokens * 16 float4
    int i = blockIdx.x * 256 + threadIdx.x;
    if (i >= N_TOKENS * 16) return;
    int tok = i >> 4, c4 = i & 15;
    int v = __ldg(&seq[tok]);
    if (v >= NUM_ITEM) v = 0;
    int pos = __ldg(&g_remap[v]);
    reinterpret_cast<float4*>(out)[(size_t)tok * 16 + c4] =
        __ldg(&reinterpret_cast<const float4*>(fused)[(size_t)pos * 16 + c4]);
}

// ------------------------- launch ------------------------------------------
static inline int grid4(long n4) { return (int)((n4 + 255) / 256); }

extern "C" void kernel_launch(void* const* d_in, const int* in_sizes, int n_in,
                              void* d_out, int out_size)
{
    const int*   seq     = (const int*)d_in[0];
    const float* content = (const float*)d_in[1];
    const float* text    = (const float*)d_in[2];
    const float* cff     = (const float*)d_in[3];
    const float* idemb   = (const float*)d_in[4];
    const float* c_w1 = (const float*)d_in[5],  *c_b1 = (const float*)d_in[6];
    const float* c_w2 = (const float*)d_in[7],  *c_b2 = (const float*)d_in[8];
    const float* c_w3 = (const float*)d_in[9],  *c_b3 = (const float*)d_in[10];
    const float* t_w1 = (const float*)d_in[11], *t_b1 = (const float*)d_in[12];
    const float* t_w2 = (const float*)d_in[13], *t_b2 = (const float*)d_in[14];
    const float* t_w3 = (const float*)d_in[15], *t_b3 = (const float*)d_in[16];
    const float* cf_w = (const float*)d_in[17], *cf_b = (const float*)d_in[18];
    const float* wq   = (const float*)d_in[19];
    const float* wk   = (const float*)d_in[20];
    const float* wv   = (const float*)d_in[21];
    float* out = (float*)d_out;

    __half *ahc, *alc, *aht, *alt, *h1h, *h1l, *h2h, *h2l;
    __half *w1c, *w1t, *w2c, *w2t, *w3c, *w3t;
    float *cemb, *temb, *cfemb, *fused;
    cudaGetSymbolAddress((void**)&ahc, g_ahc);  cudaGetSymbolAddress((void**)&alc, g_alc);
    cudaGetSymbolAddress((void**)&aht, g_aht);  cudaGetSymbolAddress((void**)&alt, g_alt);
    cudaGetSymbolAddress((void**)&h1h, g_h1h);  cudaGetSymbolAddress((void**)&h1l, g_h1l);
    cudaGetSymbolAddress((void**)&h2h, g_h2h);  cudaGetSymbolAddress((void**)&h2l, g_h2l);
    cudaGetSymbolAddress((void**)&w1c, g_w1c);  cudaGetSymbolAddress((void**)&w1t, g_w1t);
    cudaGetSymbolAddress((void**)&w2c, g_w2c);  cudaGetSymbolAddress((void**)&w2t, g_w2t);
    cudaGetSymbolAddress((void**)&w3c, g_w3c);  cudaGetSymbolAddress((void**)&w3t, g_w3t);
    cudaGetSymbolAddress((void**)&cemb,  g_cemb);
    cudaGetSymbolAddress((void**)&temb,  g_temb);
    cudaGetSymbolAddress((void**)&cfemb, g_cfemb);
    cudaGetSymbolAddress((void**)&fused, g_fused);

    const int gy = (NUM_ITEM + 127) / 128;   // 391 (worst-case M)

    const int SMEM_BN128 = 2 * (2 * 128 * 80 + 128 * 80);   // 61440
    const int SMEM_BN64  = 2 * (2 * 128 * 80 + 64 * 80);    // 51200
    cudaFuncSetAttribute((const void*)mma_gemm<128, 2, 4, true, true>,
                         cudaFuncAttributeMaxDynamicSharedMemorySize, SMEM_BN128);
    cudaFuncSetAttribute((const void*)mma_gemm<64, 4, 2, false, false>,
                         cudaFuncAttributeMaxDynamicSharedMemorySize, SMEM_BN64);
    cudaFuncSetAttribute(attn_kernel,
                         cudaFuncAttributeMaxDynamicSharedMemorySize, ATTN_SMEM_BYTES);

    // ---------------- compaction ----------------
    flag_clear_kernel<<<NBLK_SCAN, 256>>>();
    mark_kernel<<<(N_TOKENS + 255) / 256, 256>>>(seq);
    scan_p1_kernel<<<NBLK_SCAN, 256>>>();
    scan_p2_kernel<<<1, 256>>>();
    scan_p3_kernel<<<NBLK_SCAN, 256>>>();

    // ---------------- normsplits (compacted) + weight converts --------------
    normsplit_kernel<<<NUM_ITEM, 128>>>(content, 1024, ahc, alc);
    normsplit_kernel<<<NUM_ITEM, 128>>>(text, 768, aht, alt);
    convert_kernel<<<grid4(1024L * 1024 / 4), 256>>>(c_w1, 1024L * 1024 / 4, w1c);
    convert_kernel<<<grid4(256L * 1024 / 4), 256>>>(c_w2, 256L * 1024 / 4, w2c);
    convert_kernel<<<grid4(64L * 256 / 4), 256>>>(c_w3, 64L * 256 / 4, w3c);
    convert_kernel<<<grid4(768L * 768 / 4), 256>>>(t_w1, 768L * 768 / 4, w1t);
    convert_kernel<<<grid4(256L * 768 / 4), 256>>>(t_w2, 256L * 768 / 4, w2t);
    convert_kernel<<<grid4(64L * 256 / 4), 256>>>(t_w3, 64L * 256 / 4, w3t);

    // ---------------- content branch (M = g_count at runtime) ----------------
    mma_gemm<128, 2, 4, true, true><<<dim3(8, gy), 256, SMEM_BN128>>>(
        1024, 1024, ahc, alc, w1c, c_b1, nullptr, h1h, h1l);
    mma_gemm<128, 2, 4, true, true><<<dim3(2, gy), 256, SMEM_BN128>>>(
        256, 1024, h1h, h1l, w2c, c_b2, nullptr, h2h, h2l);
    mma_gemm<64, 4, 2, false, false><<<dim3(1, gy), 256, SMEM_BN64>>>(
        64, 256, h2h, h2l, w3c, c_b3, cemb, nullptr, nullptr);

    // ---------------- text branch ----------------
    mma_gemm<128, 2, 4, true, true><<<dim3(6, gy), 256, SMEM_BN128>>>(
        768, 768, aht, alt, w1t, t_b1, nullptr, h1h, h1l);
    mma_gemm<128, 2, 4, true, true><<<dim3(2, gy), 256, SMEM_BN128>>>(
        256, 768, h1h, h1l, w2t, t_b2, nullptr, h2h, h2l);
    mma_gemm<64, 4, 2, false, false><<<dim3(1, gy), 256, SMEM_BN64>>>(
        64, 256, h2h, h2l, w3t, t_b3, temb, nullptr, nullptr);

    // cf linear (compacted rows, gathered via g_items)
    sgemm_nt_gather<128, 64, 16, 8, 4><<<dim3(1, gy), 256>>>(
        64, 64, cff, cf_w, cf_b, cfemb);

    // per-unique-item attention, then scatter to tokens
    attn_kernel<<<gy, 128, ATTN_SMEM_BYTES>>>(
        cemb, temb, cfemb, idemb, wq, wk, wv, fused);
    scatter_kernel<<<(N_TOKENS * 16 + 255) / 256, 256>>>(seq, fused, out);
}